// round 5
// baseline (speedup 1.0000x reference)
#include <cuda_runtime.h>

#define NN 50000
#define MM 800000
#define HD 64

// Scratch accumulators (allocation-free: __device__ globals).
// g_accum_f[v] = {sum fx, sum fy, sum fz, degree}
__device__ float4 g_accum_f[NN];
__device__ float4 g_accum_msg[NN * 16];   // 64 floats per node

// ---------------- packed f32x2 helpers ----------------
__device__ __forceinline__ unsigned long long pack2(float v) {
    unsigned long long r;
    asm("mov.b64 %0, {%1, %1};" : "=l"(r) : "f"(v));
    return r;
}
__device__ __forceinline__ void unpack2(unsigned long long a, float& lo, float& hi) {
    asm("mov.b64 {%0, %1}, %2;" : "=f"(lo), "=f"(hi) : "l"(a));
}
__device__ __forceinline__ void ffma2(unsigned long long& acc, unsigned long long a,
                                      unsigned long long b) {
    asm("fma.rn.f32x2 %0, %1, %2, %0;" : "+l"(acc) : "l"(a), "l"(b));
}
__device__ __forceinline__ float silu_f(float x) {
    return __fdividef(x, 1.0f + __expf(-x));
}
__device__ __forceinline__ void red4(float* p, float a, float b, float c, float d) {
    asm volatile("red.global.add.v4.f32 [%0], {%1,%2,%3,%4};"
                 :: "l"(p), "f"(a), "f"(b), "f"(c), "f"(d) : "memory");
}

// acc[2p] holds outputs (4..), layout: accp[p] = outputs (2p, 2p+1).
// One weight row (64 floats, 16B-aligned in SMEM): 16 LDS.128 + 32 FFMA2.
__device__ __forceinline__ void gemm_row(unsigned long long* accp, const float* wrow,
                                         unsigned long long vv) {
    const ulonglong2* wr = (const ulonglong2*)wrow;
#pragma unroll
    for (int jj = 0; jj < 16; jj++) {
        ulonglong2 w = wr[jj];
        ffma2(accp[2 * jj], w.x, vv);
        ffma2(accp[2 * jj + 1], w.y, vv);
    }
}
__device__ __forceinline__ void gemm4(unsigned long long* accp, const float* wbase, float4 sv) {
    gemm_row(accp, wbase, pack2(sv.x));
    gemm_row(accp, wbase + 64, pack2(sv.y));
    gemm_row(accp, wbase + 128, pack2(sv.z));
    gemm_row(accp, wbase + 192, pack2(sv.w));
}
__device__ __forceinline__ void init_bias(unsigned long long* accp, const float* sB) {
    const ulonglong2* bp = (const ulonglong2*)sB;
#pragma unroll
    for (int q = 0; q < 16; q++) {
        ulonglong2 b = bp[q];
        accp[2 * q] = b.x;
        accp[2 * q + 1] = b.y;
    }
}

// ---------------- zero scratch ----------------
__global__ void zero_kernel() {
    int i = blockIdx.x * blockDim.x + threadIdx.x;
    int stride = gridDim.x * blockDim.x;
    const float4 z = make_float4(0.f, 0.f, 0.f, 0.f);
    for (int k = i; k < NN; k += stride) g_accum_f[k] = z;
    for (int k = i; k < NN * 16; k += stride) g_accum_msg[k] = z;
}

// ---------------- edge kernel ----------------
// SMEM floats: sW1 9280 | sW2 4096 | sWc1 4096 | sWc2 64 | sB1 64 | sB2 64 | sBc1 64 | tbuf 8192
#define EDGE_SMEM_FLOATS (9280 + 4096 + 4096 + 64 + 64 + 64 + 64 + 64 * 128)
#define EDGE_SMEM_BYTES (EDGE_SMEM_FLOATS * 4)

__global__ __launch_bounds__(128, 2) void edge_kernel(
    const float* __restrict__ x, const float* __restrict__ h,
    const float* __restrict__ edge_fea,
    const float* __restrict__ w1e, const float* __restrict__ b1e,
    const float* __restrict__ w2e, const float* __restrict__ b2e,
    const float* __restrict__ wc1, const float* __restrict__ bc1,
    const float* __restrict__ wc2, const float* __restrict__ bc2,
    const int* __restrict__ row, const int* __restrict__ col) {
    extern __shared__ float sm[];
    float* sW1 = sm;                  // 9280  (rows: [145][64])
    float* sW2 = sm + 9280;           // 4096
    float* sWc1 = sm + 13376;         // 4096
    float* sWc2 = sm + 17472;         // 64
    float* sB1 = sm + 17536;
    float* sB2 = sm + 17600;
    float* sBc1 = sm + 17664;
    float* tbuf = sm + 17728;         // [64][128]

    int tid = threadIdx.x;
    for (int i = tid; i < 9280; i += 128) sW1[i] = w1e[i];
    for (int i = tid; i < 4096; i += 128) sW2[i] = w2e[i];
    for (int i = tid; i < 4096; i += 128) sWc1[i] = wc1[i];
    if (tid < 64) {
        sWc2[tid] = wc2[tid];
        sB1[tid] = b1e[tid];
        sB2[tid] = b2e[tid];
        sBc1[tid] = bc1[tid];
    }
    __syncthreads();

    int e = blockIdx.x * 128 + tid;
    if (e >= MM) return;

    int r = row[e], c = col[e];
    float rx = x[3 * r] - x[3 * c];
    float ry = x[3 * r + 1] - x[3 * c + 1];
    float rz = x[3 * r + 2] - x[3 * c + 2];
    float sq = rx * rx + ry * ry + rz * rz;

    unsigned long long accp[32];

    // ---- GEMM1: s[145] @ w1e, s = [sq, h[row], h[col], edge_fea] ----
    init_bias(accp, sB1);
    gemm_row(accp, sW1, pack2(sq));  // row 0 (sq)
    {
        const float4* hr = (const float4*)(h + (size_t)r * HD);
#pragma unroll 2
        for (int k = 0; k < 16; k++) gemm4(accp, sW1 + (1 + 4 * k) * 64, __ldg(hr + k));
        const float4* hc = (const float4*)(h + (size_t)c * HD);
#pragma unroll 2
        for (int k = 0; k < 16; k++) gemm4(accp, sW1 + (65 + 4 * k) * 64, __ldg(hc + k));
        const float4* ef = (const float4*)(edge_fea + (size_t)e * 16);
#pragma unroll 2
        for (int k = 0; k < 4; k++) gemm4(accp, sW1 + (129 + 4 * k) * 64, __ldg(ef + k));
    }
    // silu -> tbuf
#pragma unroll
    for (int p = 0; p < 32; p++) {
        float lo, hi;
        unpack2(accp[p], lo, hi);
        tbuf[(2 * p) * 128 + tid] = silu_f(lo);
        tbuf[(2 * p + 1) * 128 + tid] = silu_f(hi);
    }

    // ---- GEMM2: t1 @ w2e ----
    init_bias(accp, sB2);
#pragma unroll 2
    for (int i = 0; i < 64; i++) gemm_row(accp, sW2 + i * 64, pack2(tbuf[i * 128 + tid]));

    // message = silu(.)  -> atomics + tbuf
    float* msgp = (float*)g_accum_msg + (size_t)r * HD;
#pragma unroll
    for (int g = 0; g < 16; g++) {
        float a0, a1, a2, a3;
        unpack2(accp[2 * g], a0, a1);
        unpack2(accp[2 * g + 1], a2, a3);
        a0 = silu_f(a0); a1 = silu_f(a1); a2 = silu_f(a2); a3 = silu_f(a3);
        tbuf[(4 * g) * 128 + tid] = a0;
        tbuf[(4 * g + 1) * 128 + tid] = a1;
        tbuf[(4 * g + 2) * 128 + tid] = a2;
        tbuf[(4 * g + 3) * 128 + tid] = a3;
        red4(msgp + 4 * g, a0, a1, a2, a3);
    }

    // ---- GEMM3: message @ wc1 ----
    init_bias(accp, sBc1);
#pragma unroll 2
    for (int i = 0; i < 64; i++) gemm_row(accp, sWc1 + i * 64, pack2(tbuf[i * 128 + tid]));

    // coord scalar: silu(.) dot wc2 + bc2
    float csum = __ldg(bc2);
#pragma unroll
    for (int p = 0; p < 32; p++) {
        float lo, hi;
        unpack2(accp[p], lo, hi);
        csum += silu_f(lo) * sWc2[2 * p] + silu_f(hi) * sWc2[2 * p + 1];
    }

    red4((float*)g_accum_f + (size_t)4 * r, rx * csum, ry * csum, rz * csum, 1.0f);
}

// ---------------- node kernel ----------------
// SMEM floats: sWn1 8192 | sWn2 4096 | sBn1 64 | sBn2 64 | tbuf 8192
#define NODE_SMEM_FLOATS (8192 + 4096 + 64 + 64 + 64 * 128)
#define NODE_SMEM_BYTES (NODE_SMEM_FLOATS * 4)

__global__ __launch_bounds__(128, 2) void node_kernel(
    const float* __restrict__ x, const float* __restrict__ h,
    const float* __restrict__ wn1, const float* __restrict__ bn1,
    const float* __restrict__ wn2, const float* __restrict__ bn2,
    float* __restrict__ out) {
    extern __shared__ float sm[];
    float* sWn1 = sm;           // [128][64]
    float* sWn2 = sm + 8192;    // [64][64]
    float* sBn1 = sm + 12288;
    float* sBn2 = sm + 12352;
    float* tbuf = sm + 12416;   // [64][128]

    int tid = threadIdx.x;
    for (int i = tid; i < 8192; i += 128) sWn1[i] = wn1[i];
    for (int i = tid; i < 4096; i += 128) sWn2[i] = wn2[i];
    if (tid < 64) {
        sBn1[tid] = bn1[tid];
        sBn2[tid] = bn2[tid];
    }
    __syncthreads();

    int v = blockIdx.x * 128 + tid;
    if (v >= NN) return;

    unsigned long long accp[32];
    init_bias(accp, sBn1);
    const float4* hv = (const float4*)(h + (size_t)v * HD);
#pragma unroll 2
    for (int k = 0; k < 16; k++) gemm4(accp, sWn1 + (4 * k) * 64, __ldg(hv + k));
    const float4* mv = (const float4*)((const float*)g_accum_msg + (size_t)v * HD);
#pragma unroll 2
    for (int k = 0; k < 16; k++) gemm4(accp, sWn1 + (64 + 4 * k) * 64, __ldg(mv + k));

#pragma unroll
    for (int p = 0; p < 32; p++) {
        float lo, hi;
        unpack2(accp[p], lo, hi);
        tbuf[(2 * p) * 128 + tid] = silu_f(lo);
        tbuf[(2 * p + 1) * 128 + tid] = silu_f(hi);
    }

    init_bias(accp, sBn2);
#pragma unroll 2
    for (int i = 0; i < 64; i++) gemm_row(accp, sWn2 + i * 64, pack2(tbuf[i * 128 + tid]));

    // write h_new (no final activation)
    float* out_h = out + (size_t)NN * 3;
#pragma unroll
    for (int p = 0; p < 16; p++) {
        float a0, a1, a2, a3;
        unpack2(accp[2 * p], a0, a1);
        unpack2(accp[2 * p + 1], a2, a3);
        *(float4*)(out_h + (size_t)v * HD + 4 * p) = make_float4(a0, a1, a2, a3);
    }

    // x_new = x + clip(tot_f / max(deg,1), -100, 100)
    float4 af = g_accum_f[v];
    float deg = fmaxf(af.w, 1.0f);
    float fx = fminf(fmaxf(af.x / deg, -100.f), 100.f);
    float fy = fminf(fmaxf(af.y / deg, -100.f), 100.f);
    float fz = fminf(fmaxf(af.z / deg, -100.f), 100.f);
    out[3 * v + 0] = x[3 * v + 0] + fx;
    out[3 * v + 1] = x[3 * v + 1] + fy;
    out[3 * v + 2] = x[3 * v + 2] + fz;
}

// ---------------- launch ----------------
extern "C" void kernel_launch(void* const* d_in, const int* in_sizes, int n_in,
                              void* d_out, int out_size) {
    const float* x = (const float*)d_in[0];
    const float* h = (const float*)d_in[1];
    const float* edge_fea = (const float*)d_in[2];
    const float* w1e = (const float*)d_in[3];
    const float* b1e = (const float*)d_in[4];
    const float* w2e = (const float*)d_in[5];
    const float* b2e = (const float*)d_in[6];
    const float* wc1 = (const float*)d_in[7];
    const float* bc1 = (const float*)d_in[8];
    const float* wc2 = (const float*)d_in[9];
    const float* bc2 = (const float*)d_in[10];
    const float* wn1 = (const float*)d_in[11];
    const float* bn1 = (const float*)d_in[12];
    const float* wn2 = (const float*)d_in[13];
    const float* bn2 = (const float*)d_in[14];
    const int* row = (const int*)d_in[15];
    const int* col = (const int*)d_in[16];
    float* out = (float*)d_out;

    cudaFuncSetAttribute(edge_kernel, cudaFuncAttributeMaxDynamicSharedMemorySize,
                         EDGE_SMEM_BYTES);
    cudaFuncSetAttribute(node_kernel, cudaFuncAttributeMaxDynamicSharedMemorySize,
                         NODE_SMEM_BYTES);

    zero_kernel<<<512, 256>>>();
    edge_kernel<<<(MM + 127) / 128, 128, EDGE_SMEM_BYTES>>>(
        x, h, edge_fea, w1e, b1e, w2e, b2e, wc1, bc1, wc2, bc2, row, col);
    node_kernel<<<(NN + 127) / 128, 128, NODE_SMEM_BYTES>>>(
        x, h, wn1, bn1, wn2, bn2, out);
}

// round 7
// speedup vs baseline: 1.2307x; 1.2307x over previous
#include <cuda_runtime.h>

#define NN 50000
#define MM 800000
#define HD 64

// Scratch accumulators (allocation-free: __device__ globals).
// g_accum_f[v] = {sum fx, sum fy, sum fz, degree}
__device__ float4 g_accum_f[NN];
__device__ float4 g_accum_msg[NN * 16];   // 64 floats per node

typedef unsigned long long ull;

// ---------------- packed f32x2 helpers ----------------
__device__ __forceinline__ ull pack2(float v) {
    ull r;
    asm("mov.b64 %0, {%1, %1};" : "=l"(r) : "f"(v));
    return r;
}
__device__ __forceinline__ void unpack2(ull a, float& lo, float& hi) {
    asm("mov.b64 {%0, %1}, %2;" : "=f"(lo), "=f"(hi) : "l"(a));
}
__device__ __forceinline__ void ffma2(ull& acc, ull a, ull b) {
    asm("fma.rn.f32x2 %0, %1, %2, %0;" : "+l"(acc) : "l"(a), "l"(b));
}
__device__ __forceinline__ float silu_f(float x) {
    return __fdividef(x, 1.0f + __expf(-x));
}
__device__ __forceinline__ void red4(float* p, float a, float b, float c, float d) {
    asm volatile("red.global.add.v4.f32 [%0], {%1,%2,%3,%4};"
                 :: "l"(p), "f"(a), "f"(b), "f"(c), "f"(d) : "memory");
}

// Half-row GEMV step for TWO edges: 8 LDS.128 feed 32 FFMA2.
// a0/a1: 16 ull accumulators each (32 output features of the half).
__device__ __forceinline__ void gemm_row2(ull* a0, ull* a1, const float* wrowhalf,
                                          ull v0, ull v1) {
    const ulonglong2* wr = (const ulonglong2*)wrowhalf;
#pragma unroll
    for (int q = 0; q < 8; q++) {
        ulonglong2 w = wr[q];
        ffma2(a0[2 * q], w.x, v0);
        ffma2(a0[2 * q + 1], w.y, v0);
        ffma2(a1[2 * q], w.x, v1);
        ffma2(a1[2 * q + 1], w.y, v1);
    }
}
__device__ __forceinline__ void gemm4_2(ull* a0, ull* a1, const float* wbase_half,
                                        float4 va, float4 vb) {
    gemm_row2(a0, a1, wbase_half, pack2(va.x), pack2(vb.x));
    gemm_row2(a0, a1, wbase_half + 64, pack2(va.y), pack2(vb.y));
    gemm_row2(a0, a1, wbase_half + 128, pack2(va.z), pack2(vb.z));
    gemm_row2(a0, a1, wbase_half + 192, pack2(va.w), pack2(vb.w));
}
__device__ __forceinline__ void init_bias2(ull* a0, ull* a1, const float* sBhalf) {
    const ulonglong2* bp = (const ulonglong2*)sBhalf;
#pragma unroll
    for (int q = 0; q < 8; q++) {
        ulonglong2 b = bp[q];
        a0[2 * q] = b.x;
        a0[2 * q + 1] = b.y;
        a1[2 * q] = b.x;
        a1[2 * q + 1] = b.y;
    }
}

// ---------------- zero scratch ----------------
__global__ void zero_kernel() {
    int i = blockIdx.x * blockDim.x + threadIdx.x;
    int stride = gridDim.x * blockDim.x;
    const float4 z = make_float4(0.f, 0.f, 0.f, 0.f);
    for (int k = i; k < NN; k += stride) g_accum_f[k] = z;
    for (int k = i; k < NN * 16; k += stride) g_accum_msg[k] = z;
}

// ---------------- edge kernel ----------------
// 128 threads process 128 edges: thread (half = tid>>6, j = tid&63) computes
// output features [32*half, 32*half+32) of edges (2j, 2j+1).
// SMEM floats: sW1 9280 | sW2 4096 | sWc1 4096 | sWc2 64 | sB1 64 | sB2 64 | sBc1 64 | tbuf 8192
#define EDGE_SMEM_FLOATS (9280 + 4096 + 4096 + 64 + 64 + 64 + 64 + 64 * 128)
#define EDGE_SMEM_BYTES (EDGE_SMEM_FLOATS * 4)

__global__ __launch_bounds__(128, 2) void edge_kernel(
    const float* __restrict__ x, const float* __restrict__ h,
    const float* __restrict__ edge_fea,
    const float* __restrict__ w1e, const float* __restrict__ b1e,
    const float* __restrict__ w2e, const float* __restrict__ b2e,
    const float* __restrict__ wc1, const float* __restrict__ bc1,
    const float* __restrict__ wc2, const float* __restrict__ bc2,
    const int* __restrict__ row, const int* __restrict__ col) {
    extern __shared__ float sm[];
    float* sW1 = sm;                  // [145][64]
    float* sW2 = sm + 9280;           // [64][64]
    float* sWc1 = sm + 13376;         // [64][64]
    float* sWc2 = sm + 17472;         // 64
    float* sB1 = sm + 17536;
    float* sB2 = sm + 17600;
    float* sBc1 = sm + 17664;
    float* tbuf = sm + 17728;         // [64][128]

    int tid = threadIdx.x;
    for (int i = tid; i < 9280; i += 128) sW1[i] = w1e[i];
    for (int i = tid; i < 4096; i += 128) sW2[i] = w2e[i];
    for (int i = tid; i < 4096; i += 128) sWc1[i] = wc1[i];
    if (tid < 64) {
        sWc2[tid] = wc2[tid];
        sB1[tid] = b1e[tid];
        sB2[tid] = b2e[tid];
        sBc1[tid] = bc1[tid];
    }
    __syncthreads();                                   // S1

    const int half = tid >> 6;
    const int j = tid & 63;
    const int hoff = half * 32;
    const int e0 = blockIdx.x * 128 + 2 * j;           // e1 = e0 + 1

    int2 rr = *(const int2*)(row + e0);
    int2 cc = *(const int2*)(col + e0);
    const int r0 = rr.x, r1 = rr.y;
    const int c0 = cc.x, c1 = cc.y;

    float rx0 = x[3 * r0] - x[3 * c0];
    float ry0 = x[3 * r0 + 1] - x[3 * c0 + 1];
    float rz0 = x[3 * r0 + 2] - x[3 * c0 + 2];
    float rx1 = x[3 * r1] - x[3 * c1];
    float ry1 = x[3 * r1 + 1] - x[3 * c1 + 1];
    float rz1 = x[3 * r1 + 2] - x[3 * c1 + 2];
    float sq0 = rx0 * rx0 + ry0 * ry0 + rz0 * rz0;
    float sq1 = rx1 * rx1 + ry1 * ry1 + rz1 * rz1;

    ull acc0[16], acc1[16];

    // ---- GEMM1: s[145] @ w1e, s = [sq, h[row], h[col], edge_fea] ----
    const float* W1 = sW1 + hoff;
    init_bias2(acc0, acc1, sB1 + hoff);
    gemm_row2(acc0, acc1, W1, pack2(sq0), pack2(sq1));
    {
        const float4* hr0 = (const float4*)(h + (size_t)r0 * HD);
        const float4* hr1 = (const float4*)(h + (size_t)r1 * HD);
#pragma unroll 2
        for (int k = 0; k < 16; k++)
            gemm4_2(acc0, acc1, W1 + (1 + 4 * k) * 64, __ldg(hr0 + k), __ldg(hr1 + k));
        const float4* hc0 = (const float4*)(h + (size_t)c0 * HD);
        const float4* hc1 = (const float4*)(h + (size_t)c1 * HD);
#pragma unroll 2
        for (int k = 0; k < 16; k++)
            gemm4_2(acc0, acc1, W1 + (65 + 4 * k) * 64, __ldg(hc0 + k), __ldg(hc1 + k));
        const float4* ef0 = (const float4*)(edge_fea + (size_t)e0 * 16);
        const float4* ef1 = (const float4*)(edge_fea + (size_t)(e0 + 1) * 16);
#pragma unroll 2
        for (int k = 0; k < 4; k++)
            gemm4_2(acc0, acc1, W1 + (129 + 4 * k) * 64, __ldg(ef0 + k), __ldg(ef1 + k));
    }
    // silu -> tbuf (feature-major; edges e0,e1 in adjacent columns => float2 STS)
#pragma unroll
    for (int q = 0; q < 16; q++) {
        float a, b, c, d;
        unpack2(acc0[q], a, b);
        unpack2(acc1[q], c, d);
        int f = hoff + 2 * q;
        *(float2*)&tbuf[f * 128 + 2 * j] = make_float2(silu_f(a), silu_f(c));
        *(float2*)&tbuf[(f + 1) * 128 + 2 * j] = make_float2(silu_f(b), silu_f(d));
    }
    __syncthreads();                                   // S2

    // ---- GEMM2: t1 @ w2e ----
    init_bias2(acc0, acc1, sB2 + hoff);
#pragma unroll 2
    for (int i = 0; i < 64; i++) {
        float2 tv = *(const float2*)&tbuf[i * 128 + 2 * j];
        gemm_row2(acc0, acc1, sW2 + i * 64 + hoff, pack2(tv.x), pack2(tv.y));
    }
    __syncthreads();                                   // S3 (tbuf reads done)

    // message = silu(.)  -> global atomics + tbuf
    {
        float* msgp0 = (float*)g_accum_msg + (size_t)r0 * HD + hoff;
        float* msgp1 = (float*)g_accum_msg + (size_t)r1 * HD + hoff;
#pragma unroll
        for (int q = 0; q < 8; q++) {
            float a0v, a1v, a2v, a3v, b0v, b1v, b2v, b3v;
            unpack2(acc0[2 * q], a0v, a1v);
            unpack2(acc0[2 * q + 1], a2v, a3v);
            unpack2(acc1[2 * q], b0v, b1v);
            unpack2(acc1[2 * q + 1], b2v, b3v);
            a0v = silu_f(a0v); a1v = silu_f(a1v); a2v = silu_f(a2v); a3v = silu_f(a3v);
            b0v = silu_f(b0v); b1v = silu_f(b1v); b2v = silu_f(b2v); b3v = silu_f(b3v);
            int f = hoff + 4 * q;
            *(float2*)&tbuf[f * 128 + 2 * j] = make_float2(a0v, b0v);
            *(float2*)&tbuf[(f + 1) * 128 + 2 * j] = make_float2(a1v, b1v);
            *(float2*)&tbuf[(f + 2) * 128 + 2 * j] = make_float2(a2v, b2v);
            *(float2*)&tbuf[(f + 3) * 128 + 2 * j] = make_float2(a3v, b3v);
            red4(msgp0 + 4 * q, a0v, a1v, a2v, a3v);
            red4(msgp1 + 4 * q, b0v, b1v, b2v, b3v);
        }
    }
    __syncthreads();                                   // S4

    // ---- GEMM3: message @ wc1 ----
    init_bias2(acc0, acc1, sBc1 + hoff);
#pragma unroll 2
    for (int i = 0; i < 64; i++) {
        float2 tv = *(const float2*)&tbuf[i * 128 + 2 * j];
        gemm_row2(acc0, acc1, sWc1 + i * 64 + hoff, pack2(tv.x), pack2(tv.y));
    }

    // coord scalar partials: silu(.) dot wc2 (per-half)
    float p0 = 0.f, p1 = 0.f;
#pragma unroll
    for (int q = 0; q < 16; q++) {
        float a, b, c, d;
        unpack2(acc0[q], a, b);
        unpack2(acc1[q], c, d);
        float w0 = sWc2[hoff + 2 * q], w1v = sWc2[hoff + 2 * q + 1];
        p0 += silu_f(a) * w0 + silu_f(b) * w1v;
        p1 += silu_f(c) * w0 + silu_f(d) * w1v;
    }
    __syncthreads();                                   // S5 (GEMM3 tbuf reads done)
    tbuf[(2 * j) * 2 + half] = p0;
    tbuf[(2 * j + 1) * 2 + half] = p1;
    __syncthreads();                                   // S6

    // Each thread finalizes one edge: half 0 -> e0 (even), half 1 -> e1 (odd).
    int m = 2 * j + half;
    float csum = tbuf[m * 2] + tbuf[m * 2 + 1] + __ldg(bc2);
    float rxm = half ? rx1 : rx0;
    float rym = half ? ry1 : ry0;
    float rzm = half ? rz1 : rz0;
    int rm = half ? r1 : r0;
    red4((float*)g_accum_f + (size_t)4 * rm, rxm * csum, rym * csum, rzm * csum, 1.0f);
}

// ---------------- node kernel ----------------
__device__ __forceinline__ void gemm_row(ull* accp, const float* wrow, ull vv) {
    const ulonglong2* wr = (const ulonglong2*)wrow;
#pragma unroll
    for (int jj = 0; jj < 16; jj++) {
        ulonglong2 w = wr[jj];
        ffma2(accp[2 * jj], w.x, vv);
        ffma2(accp[2 * jj + 1], w.y, vv);
    }
}
__device__ __forceinline__ void gemm4(ull* accp, const float* wbase, float4 sv) {
    gemm_row(accp, wbase, pack2(sv.x));
    gemm_row(accp, wbase + 64, pack2(sv.y));
    gemm_row(accp, wbase + 128, pack2(sv.z));
    gemm_row(accp, wbase + 192, pack2(sv.w));
}
__device__ __forceinline__ void init_bias(ull* accp, const float* sB) {
    const ulonglong2* bp = (const ulonglong2*)sB;
#pragma unroll
    for (int q = 0; q < 16; q++) {
        ulonglong2 b = bp[q];
        accp[2 * q] = b.x;
        accp[2 * q + 1] = b.y;
    }
}

// SMEM floats: sWn1 8192 | sWn2 4096 | sBn1 64 | sBn2 64 | tbuf 8192
#define NODE_SMEM_FLOATS (8192 + 4096 + 64 + 64 + 64 * 128)
#define NODE_SMEM_BYTES (NODE_SMEM_FLOATS * 4)

__global__ __launch_bounds__(128, 2) void node_kernel(
    const float* __restrict__ x, const float* __restrict__ h,
    const float* __restrict__ wn1, const float* __restrict__ bn1,
    const float* __restrict__ wn2, const float* __restrict__ bn2,
    float* __restrict__ out) {
    extern __shared__ float sm[];
    float* sWn1 = sm;           // [128][64]
    float* sWn2 = sm + 8192;    // [64][64]
    float* sBn1 = sm + 12288;
    float* sBn2 = sm + 12352;
    float* tbuf = sm + 12416;   // [64][128]

    int tid = threadIdx.x;
    for (int i = tid; i < 8192; i += 128) sWn1[i] = wn1[i];
    for (int i = tid; i < 4096; i += 128) sWn2[i] = wn2[i];
    if (tid < 64) {
        sBn1[tid] = bn1[tid];
        sBn2[tid] = bn2[tid];
    }
    __syncthreads();

    int v = blockIdx.x * 128 + tid;
    if (v >= NN) return;

    ull accp[32];
    init_bias(accp, sBn1);
    const float4* hv = (const float4*)(h + (size_t)v * HD);
#pragma unroll 2
    for (int k = 0; k < 16; k++) gemm4(accp, sWn1 + (4 * k) * 64, __ldg(hv + k));
    const float4* mv = (const float4*)((const float*)g_accum_msg + (size_t)v * HD);
#pragma unroll 2
    for (int k = 0; k < 16; k++) gemm4(accp, sWn1 + (64 + 4 * k) * 64, __ldg(mv + k));

#pragma unroll
    for (int p = 0; p < 32; p++) {
        float lo, hi;
        unpack2(accp[p], lo, hi);
        tbuf[(2 * p) * 128 + tid] = silu_f(lo);
        tbuf[(2 * p + 1) * 128 + tid] = silu_f(hi);
    }

    init_bias(accp, sBn2);
#pragma unroll 2
    for (int i = 0; i < 64; i++) gemm_row(accp, sWn2 + i * 64, pack2(tbuf[i * 128 + tid]));

    // write h_new (no final activation)
    float* out_h = out + (size_t)NN * 3;
#pragma unroll
    for (int p = 0; p < 16; p++) {
        float a0, a1, a2, a3;
        unpack2(accp[2 * p], a0, a1);
        unpack2(accp[2 * p + 1], a2, a3);
        *(float4*)(out_h + (size_t)v * HD + 4 * p) = make_float4(a0, a1, a2, a3);
    }

    // x_new = x + clip(tot_f / max(deg,1), -100, 100)
    float4 af = g_accum_f[v];
    float deg = fmaxf(af.w, 1.0f);
    float fx = fminf(fmaxf(af.x / deg, -100.f), 100.f);
    float fy = fminf(fmaxf(af.y / deg, -100.f), 100.f);
    float fz = fminf(fmaxf(af.z / deg, -100.f), 100.f);
    out[3 * v + 0] = x[3 * v + 0] + fx;
    out[3 * v + 1] = x[3 * v + 1] + fy;
    out[3 * v + 2] = x[3 * v + 2] + fz;
}

// ---------------- launch ----------------
extern "C" void kernel_launch(void* const* d_in, const int* in_sizes, int n_in,
                              void* d_out, int out_size) {
    const float* x = (const float*)d_in[0];
    const float* h = (const float*)d_in[1];
    const float* edge_fea = (const float*)d_in[2];
    const float* w1e = (const float*)d_in[3];
    const float* b1e = (const float*)d_in[4];
    const float* w2e = (const float*)d_in[5];
    const float* b2e = (const float*)d_in[6];
    const float* wc1 = (const float*)d_in[7];
    const float* bc1 = (const float*)d_in[8];
    const float* wc2 = (const float*)d_in[9];
    const float* bc2 = (const float*)d_in[10];
    const float* wn1 = (const float*)d_in[11];
    const float* bn1 = (const float*)d_in[12];
    const float* wn2 = (const float*)d_in[13];
    const float* bn2 = (const float*)d_in[14];
    const int* row = (const int*)d_in[15];
    const int* col = (const int*)d_in[16];
    float* out = (float*)d_out;

    cudaFuncSetAttribute(edge_kernel, cudaFuncAttributeMaxDynamicSharedMemorySize,
                         EDGE_SMEM_BYTES);
    cudaFuncSetAttribute(node_kernel, cudaFuncAttributeMaxDynamicSharedMemorySize,
                         NODE_SMEM_BYTES);

    zero_kernel<<<512, 256>>>();
    edge_kernel<<<MM / 128, 128, EDGE_SMEM_BYTES>>>(
        x, h, edge_fea, w1e, b1e, w2e, b2e, wc1, bc1, wc2, bc2, row, col);
    node_kernel<<<(NN + 127) / 128, 128, NODE_SMEM_BYTES>>>(
        x, h, wn1, bn1, wn2, bn2, out);
}

// round 12
// speedup vs baseline: 1.3116x; 1.0658x over previous
#include <cuda_runtime.h>
#include <cuda_bf16.h>
#include <cstdint>

#define NN 50000
#define MM 800000
#define HD 64
#define NB (MM / 128)

// Does this compilation pass target the architecture-specific sm_103a feature set?
#if defined(__CUDA_ARCH__) && (defined(__CUDA_ARCH_FEAT_SM103_ALL) || \
    (defined(__CUDA_ARCH_SPECIFIC__) && (__CUDA_ARCH__ == 1030)))
#define EDGE_TC 1
#else
#define EDGE_TC 0
#endif

// ---------------- device scratch (allocation-free) ----------------
__device__ float4 g_accum_f[NN];            // {fx, fy, fz, deg}
__device__ float4 g_accum_msg[NN * 16];     // 64 floats / node

// Pre-swizzled bf16 weight images (exact SMEM layout; linear copy per block)
__device__ uint4 g_W1hi[1536];   // [64 n, 192 k] bf16, SW128 blocked atoms (24576 B)
__device__ uint4 g_W1lo[1536];
__device__ uint4 g_W2hi[512];    // [64, 64]  (8192 B)
__device__ uint4 g_W2lo[512];
__device__ uint4 g_Wc1hi[512];
__device__ uint4 g_Wc1lo[512];

// ---------------- shared helpers ----------------
typedef unsigned long long ull;
__device__ __forceinline__ ull pack2(float v) {
    ull r;
    asm("mov.b64 %0, {%1, %1};" : "=l"(r) : "f"(v));
    return r;
}
__device__ __forceinline__ void unpack2(ull a, float& lo, float& hi) {
    asm("mov.b64 {%0, %1}, %2;" : "=f"(lo), "=f"(hi) : "l"(a));
}
__device__ __forceinline__ void ffma2(ull& acc, ull a, ull b) {
    asm("fma.rn.f32x2 %0, %1, %2, %0;" : "+l"(acc) : "l"(a), "l"(b));
}
__device__ __forceinline__ float silu_f(float x) {
    return __fdividef(x, 1.0f + __expf(-x));
}
__device__ __forceinline__ void red4(float* p, float a, float b, float c, float d) {
    asm volatile("red.global.add.v4.f32 [%0], {%1,%2,%3,%4};"
                 :: "l"(p), "f"(a), "f"(b), "f"(c), "f"(d) : "memory");
}

// bf16 hi/lo split of a pair (low half of u32 = even-k element)
__device__ __forceinline__ void split2(float a, float b, uint32_t& hi, uint32_t& lo) {
    __nv_bfloat16 ha = __float2bfloat16(a), hb = __float2bfloat16(b);
    hi = (uint32_t)__bfloat16_as_ushort(ha) | ((uint32_t)__bfloat16_as_ushort(hb) << 16);
    float la = a - __bfloat162float(ha), lb = b - __bfloat162float(hb);
    lo = (uint32_t)__bfloat16_as_ushort(__float2bfloat16(la)) |
         ((uint32_t)__bfloat16_as_ushort(__float2bfloat16(lb)) << 16);
}

// swizzled byte offset inside a B weight image [64 rows(n), K cols] blocked-atom SW128
__device__ __forceinline__ uint32_t boff(int n, int k) {
    uint32_t atom = (uint32_t)((k >> 6) * 8 + (n >> 3));
    uint32_t b = atom * 1024u + (uint32_t)(n & 7) * 128u + (uint32_t)(k & 63) * 2u;
    return b ^ ((b >> 3) & 0x70);
}

// ---------------- fp32x2 GEMV helpers (fallback edge + node kernel) ----------------
__device__ __forceinline__ void gemm_row2(ull* a0, ull* a1, const float* wrowhalf,
                                          ull v0, ull v1) {
    const ulonglong2* wr = (const ulonglong2*)wrowhalf;
#pragma unroll
    for (int q = 0; q < 8; q++) {
        ulonglong2 w = wr[q];
        ffma2(a0[2 * q], w.x, v0);
        ffma2(a0[2 * q + 1], w.y, v0);
        ffma2(a1[2 * q], w.x, v1);
        ffma2(a1[2 * q + 1], w.y, v1);
    }
}
__device__ __forceinline__ void gemm4_2(ull* a0, ull* a1, const float* wbase_half,
                                        float4 va, float4 vb) {
    gemm_row2(a0, a1, wbase_half, pack2(va.x), pack2(vb.x));
    gemm_row2(a0, a1, wbase_half + 64, pack2(va.y), pack2(vb.y));
    gemm_row2(a0, a1, wbase_half + 128, pack2(va.z), pack2(vb.z));
    gemm_row2(a0, a1, wbase_half + 192, pack2(va.w), pack2(vb.w));
}
__device__ __forceinline__ void init_bias2(ull* a0, ull* a1, const float* sBhalf) {
    const ulonglong2* bp = (const ulonglong2*)sBhalf;
#pragma unroll
    for (int q = 0; q < 8; q++) {
        ulonglong2 b = bp[q];
        a0[2 * q] = b.x;
        a0[2 * q + 1] = b.y;
        a1[2 * q] = b.x;
        a1[2 * q + 1] = b.y;
    }
}
__device__ __forceinline__ void gemm_row(ull* accp, const float* wrow, ull vv) {
    const ulonglong2* wr = (const ulonglong2*)wrow;
#pragma unroll
    for (int jj = 0; jj < 16; jj++) {
        ulonglong2 w = wr[jj];
        ffma2(accp[2 * jj], w.x, vv);
        ffma2(accp[2 * jj + 1], w.y, vv);
    }
}
__device__ __forceinline__ void gemm4(ull* accp, const float* wbase, float4 sv) {
    gemm_row(accp, wbase, pack2(sv.x));
    gemm_row(accp, wbase + 64, pack2(sv.y));
    gemm_row(accp, wbase + 128, pack2(sv.z));
    gemm_row(accp, wbase + 192, pack2(sv.w));
}
__device__ __forceinline__ void init_bias(ull* accp, const float* sB) {
    const ulonglong2* bp = (const ulonglong2*)sB;
#pragma unroll
    for (int q = 0; q < 16; q++) {
        ulonglong2 b = bp[q];
        accp[2 * q] = b.x;
        accp[2 * q + 1] = b.y;
    }
}

// ---------------- tcgen05 PTX helpers (only expanded under EDGE_TC) ----------------
__device__ __forceinline__ uint32_t smem_u32(const void* p) {
    uint32_t a;
    asm("{ .reg .u64 t; cvta.to.shared.u64 t, %1; cvt.u32.u64 %0, t; }" : "=r"(a) : "l"(p));
    return a;
}
__device__ __forceinline__ uint32_t elect_one_pred() {
    uint32_t p;
    asm volatile("{\n\t.reg .pred p;\n\telect.sync _|p, 0xFFFFFFFF;\n\tselp.b32 %0, 1, 0, p;\n\t}" : "=r"(p));
    return p;
}

#define TCG_ALLOC(sm, n)  asm volatile("tcgen05.alloc.cta_group::1.sync.aligned.shared::cta.b32 [%0], %1;" :: "r"((uint32_t)(sm)), "r"((uint32_t)(n)) : "memory")
#define TCG_DEALLOC(t, n) asm volatile("tcgen05.dealloc.cta_group::1.sync.aligned.b32 %0, %1;" :: "r"(t), "r"((uint32_t)(n)))
#define TCG_WAIT_ST()     asm volatile("tcgen05.wait::st.sync.aligned;" ::: "memory")
#define TCG_WAIT_LD()     asm volatile("tcgen05.wait::ld.sync.aligned;" ::: "memory")
#define TCG_FENCE_BEFORE() asm volatile("tcgen05.fence::before_thread_sync;" ::: "memory")
#define TCG_FENCE_AFTER()  asm volatile("tcgen05.fence::after_thread_sync;" ::: "memory")
#define TCG_COMMIT(mb)    asm volatile("tcgen05.commit.cta_group::1.mbarrier::arrive::one.shared::cluster.b64 [%0];" :: "r"((uint32_t)(mb)) : "memory")
#define MBAR_INIT(mb, n)  asm volatile("mbarrier.init.shared.b64 [%0], %1;" :: "r"((uint32_t)(mb)), "r"((uint32_t)(n)) : "memory")
#define MBAR_INVAL(mb)    asm volatile("mbarrier.inval.shared.b64 [%0];" :: "r"((uint32_t)(mb)) : "memory")

#define MBAR_WAIT(mb, par) do {                                                      \
    uint32_t _m = (uint32_t)(mb), _p = (uint32_t)(par), _d;                          \
    asm volatile("{\n\t.reg .pred p;\n\t"                                            \
        "mbarrier.try_wait.parity.acquire.cta.shared::cta.b64 p, [%1], %2;\n\t"      \
        "selp.b32 %0, 1, 0, p;\n\t}" : "=r"(_d) : "r"(_m), "r"(_p) : "memory");      \
    if (!_d) {                                                                       \
        asm volatile("{\n\t.reg .pred P1;\n\t"                                       \
            "WL_%=:\n\t"                                                             \
            "mbarrier.try_wait.parity.acquire.cta.shared::cta.b64 P1, [%0], %1, 0x989680;\n\t" \
            "@P1 bra.uni WD_%=;\n\tbra.uni WL_%=;\n\tWD_%=:\n\t}"                    \
            :: "r"(_m), "r"(_p) : "memory");                                         \
    }                                                                                \
} while (0)

#define TCG_ST32(addr, r)                                                            \
    asm volatile("tcgen05.st.sync.aligned.32x32b.x32.b32 [%0], "                     \
        "{%1, %2, %3, %4, %5, %6, %7, %8, %9, %10, %11, %12, %13, %14, %15, %16, "   \
        " %17, %18, %19, %20, %21, %22, %23, %24, %25, %26, %27, %28, %29, %30, %31, %32};" \
        :: "r"(addr),                                                                \
           "r"((r)[0]), "r"((r)[1]), "r"((r)[2]), "r"((r)[3]),                       \
           "r"((r)[4]), "r"((r)[5]), "r"((r)[6]), "r"((r)[7]),                       \
           "r"((r)[8]), "r"((r)[9]), "r"((r)[10]), "r"((r)[11]),                     \
           "r"((r)[12]), "r"((r)[13]), "r"((r)[14]), "r"((r)[15]),                   \
           "r"((r)[16]), "r"((r)[17]), "r"((r)[18]), "r"((r)[19]),                   \
           "r"((r)[20]), "r"((r)[21]), "r"((r)[22]), "r"((r)[23]),                   \
           "r"((r)[24]), "r"((r)[25]), "r"((r)[26]), "r"((r)[27]),                   \
           "r"((r)[28]), "r"((r)[29]), "r"((r)[30]), "r"((r)[31]) : "memory")

#define TCG_LD32(r, addr)                                                            \
    asm volatile("tcgen05.ld.sync.aligned.32x32b.x32.b32 "                           \
        "{%0, %1, %2, %3, %4, %5, %6, %7, %8, %9, %10, %11, %12, %13, %14, %15, "    \
        " %16, %17, %18, %19, %20, %21, %22, %23, %24, %25, %26, %27, %28, %29, %30, %31}, [%32];" \
        : "=r"((r)[0]), "=r"((r)[1]), "=r"((r)[2]), "=r"((r)[3]),                    \
          "=r"((r)[4]), "=r"((r)[5]), "=r"((r)[6]), "=r"((r)[7]),                    \
          "=r"((r)[8]), "=r"((r)[9]), "=r"((r)[10]), "=r"((r)[11]),                  \
          "=r"((r)[12]), "=r"((r)[13]), "=r"((r)[14]), "=r"((r)[15]),                \
          "=r"((r)[16]), "=r"((r)[17]), "=r"((r)[18]), "=r"((r)[19]),                \
          "=r"((r)[20]), "=r"((r)[21]), "=r"((r)[22]), "=r"((r)[23]),                \
          "=r"((r)[24]), "=r"((r)[25]), "=r"((r)[26]), "=r"((r)[27]),                \
          "=r"((r)[28]), "=r"((r)[29]), "=r"((r)[30]), "=r"((r)[31])                 \
        : "r"(addr))

// idesc kind::f16: F32 dtype, BF16 a/b, N=64 (8<<17), M=128 (8<<24)
#define IDESC_F16 0x8100490u

#if EDGE_TC
__device__ __forceinline__ void mma_f16(uint32_t d, uint32_t a, uint64_t bdesc, bool acc) {
    uint32_t en = acc ? 1u : 0u, z = 0u;
    asm volatile("{\n\t.reg .pred p;\n\tsetp.ne.u32 p, %4, 0;\n\t"
        "tcgen05.mma.cta_group::1.kind::f16 [%0], [%1], %2, %3, {%5, %5, %5, %5}, p;\n\t}"
        :: "r"(d), "r"(a), "l"(bdesc), "r"(IDESC_F16), "r"(en), "r"(z) : "memory");
}
#endif

// SW128 K-major descriptor base (LBO=1, SBO=64, version 1)
static constexpr uint64_t DESC_BASE_SW128 =
    (uint64_t(2) << 61) | (uint64_t(1) << 46) | (uint64_t(64) << 32) | (uint64_t(1) << 16);
__device__ __forceinline__ uint64_t mk_desc(uint32_t addr) {
    return DESC_BASE_SW128 | ((uint64_t)(addr >> 4) & 0x3FFF);
}

// ---------------- zero scratch ----------------
__global__ void zero_kernel() {
    int i = blockIdx.x * blockDim.x + threadIdx.x;
    int stride = gridDim.x * blockDim.x;
    const float4 z = make_float4(0.f, 0.f, 0.f, 0.f);
    for (int k = i; k < NN; k += stride) g_accum_f[k] = z;
    for (int k = i; k < NN * 16; k += stride) g_accum_msg[k] = z;
}

// ---------------- weight prep: transpose + bf16 split + swizzle ----------------
// B[n][k] = W[k_src][n].  s reorder: k 0..63 = h_row, 64..127 = h_col,
// 128..143 = ef, 144 = sq, rest 0  => k<=143 -> w1e row 1+k ; k==144 -> w1e row 0.
__global__ void prep_kernel(const float* __restrict__ w1e, const float* __restrict__ w2e,
                            const float* __restrict__ wc1) {
    int i = blockIdx.x * blockDim.x + threadIdx.x;
    int stride = gridDim.x * blockDim.x;
    uint8_t* w1h = (uint8_t*)g_W1hi; uint8_t* w1l = (uint8_t*)g_W1lo;
    uint8_t* w2h = (uint8_t*)g_W2hi; uint8_t* w2l = (uint8_t*)g_W2lo;
    uint8_t* wch = (uint8_t*)g_Wc1hi; uint8_t* wcl = (uint8_t*)g_Wc1lo;
    for (int idx = i; idx < 64 * 192; idx += stride) {
        int n = idx / 192, k = idx % 192;
        float f = 0.f;
        if (k <= 143) f = w1e[(1 + k) * 64 + n];
        else if (k == 144) f = w1e[n];
        __nv_bfloat16 h = __float2bfloat16(f);
        float lo = f - __bfloat162float(h);
        uint32_t o = boff(n, k);
        *(__nv_bfloat16*)(w1h + o) = h;
        *(__nv_bfloat16*)(w1l + o) = __float2bfloat16(lo);
    }
    for (int idx = i; idx < 64 * 64; idx += stride) {
        int n = idx / 64, k = idx % 64;
        uint32_t o = boff(n, k);
        float f = w2e[k * 64 + n];
        __nv_bfloat16 h = __float2bfloat16(f);
        *(__nv_bfloat16*)(w2h + o) = h;
        *(__nv_bfloat16*)(w2l + o) = __float2bfloat16(f - __bfloat162float(h));
        float g = wc1[k * 64 + n];
        __nv_bfloat16 hg = __float2bfloat16(g);
        *(__nv_bfloat16*)(wch + o) = hg;
        *(__nv_bfloat16*)(wcl + o) = __float2bfloat16(g - __bfloat162float(hg));
    }
}

// ---------------- edge kernel: tcgen05 (sm_103a pass) or fp32x2 fallback ----------------
// tc layout (bytes): tmem ptr 0 | mbar 8 | biases 16..1039 | weight images 4096..86016
#define SO_TMEM 0
#define SO_MBAR 8
#define SO_B1   16
#define SO_B2   272
#define SO_BC1  528
#define SO_WC2  784
#define SO_W1HI 4096
#define SO_W1LO 28672
#define SO_W2HI 53248
#define SO_W2LO 61440
#define SO_WC1HI 69632
#define SO_WC1LO 77824
// fallback layout (floats): sW1 9280 | sW2 4096 | sWc1 4096 | sWc2/sB1/sB2/sBc1 64*4 | tbuf 8192
#define EDGE_SMEM_BYTES ((9280 + 4096 + 4096 + 4 * 64 + 64 * 128) * 4)   // 103680 >= 86016

__global__ __launch_bounds__(128, 2) void edge_kernel(
    const float* __restrict__ x, const float* __restrict__ h,
    const float* __restrict__ edge_fea,
    const float* __restrict__ w1e, const float* __restrict__ b1e,
    const float* __restrict__ w2e, const float* __restrict__ b2e,
    const float* __restrict__ wc1, const float* __restrict__ bc1,
    const float* __restrict__ wc2, const float* __restrict__ bc2,
    const int* __restrict__ row, const int* __restrict__ col) {
#if EDGE_TC
    // ================= tcgen05 path =================
    extern __shared__ uint8_t sm[];
    const uint32_t smb = smem_u32(sm);
    const int tid = threadIdx.x;
    const int wid = tid >> 5;
    const uint32_t woff = (uint32_t)wid << 21;

    {
        uint4* d;
        d = (uint4*)(sm + SO_W1HI);
        for (int i = tid; i < 1536; i += 128) d[i] = g_W1hi[i];
        d = (uint4*)(sm + SO_W1LO);
        for (int i = tid; i < 1536; i += 128) d[i] = g_W1lo[i];
        d = (uint4*)(sm + SO_W2HI);
        for (int i = tid; i < 512; i += 128) d[i] = g_W2hi[i];
        d = (uint4*)(sm + SO_W2LO);
        for (int i = tid; i < 512; i += 128) d[i] = g_W2lo[i];
        d = (uint4*)(sm + SO_WC1HI);
        for (int i = tid; i < 512; i += 128) d[i] = g_Wc1hi[i];
        d = (uint4*)(sm + SO_WC1LO);
        for (int i = tid; i < 512; i += 128) d[i] = g_Wc1lo[i];
    }
    float* sB1 = (float*)(sm + SO_B1);
    float* sB2 = (float*)(sm + SO_B2);
    float* sBc1 = (float*)(sm + SO_BC1);
    float* sWc2 = (float*)(sm + SO_WC2);
    if (tid < 64) {
        sB1[tid] = b1e[tid];
        sB2[tid] = b2e[tid];
        sBc1[tid] = bc1[tid];
        sWc2[tid] = wc2[tid];
    }
    if (wid == 0) TCG_ALLOC(smb + SO_TMEM, 256);
    if (tid == 0) MBAR_INIT(smb + SO_MBAR, 1);
    __syncthreads();
    uint32_t tb;
    asm volatile("ld.shared.b32 %0, [%1];" : "=r"(tb) : "r"(smb + SO_TMEM));

    const int e = blockIdx.x * 128 + tid;
    const int r = row[e], c = col[e];
    const float rx = x[3 * r] - x[3 * c];
    const float ry = x[3 * r + 1] - x[3 * c + 1];
    const float rz = x[3 * r + 2] - x[3 * c + 2];
    const float sq = rx * rx + ry * ry + rz * rz;

    {
        uint32_t ahi[32], alo[32];
        const float4* hr = (const float4*)(h + (size_t)r * HD);
#pragma unroll
        for (int q = 0; q < 16; q++) {
            float4 v = __ldg(hr + q);
            split2(v.x, v.y, ahi[2 * q], alo[2 * q]);
            split2(v.z, v.w, ahi[2 * q + 1], alo[2 * q + 1]);
        }
        TCG_ST32(tb + 0 + woff, ahi);
        TCG_ST32(tb + 96 + woff, alo);
        const float4* hc = (const float4*)(h + (size_t)c * HD);
#pragma unroll
        for (int q = 0; q < 16; q++) {
            float4 v = __ldg(hc + q);
            split2(v.x, v.y, ahi[2 * q], alo[2 * q]);
            split2(v.z, v.w, ahi[2 * q + 1], alo[2 * q + 1]);
        }
        TCG_ST32(tb + 32 + woff, ahi);
        TCG_ST32(tb + 96 + 32 + woff, alo);
        const float4* ef = (const float4*)(edge_fea + (size_t)e * 16);
#pragma unroll
        for (int q = 0; q < 4; q++) {
            float4 v = __ldg(ef + q);
            split2(v.x, v.y, ahi[2 * q], alo[2 * q]);
            split2(v.z, v.w, ahi[2 * q + 1], alo[2 * q + 1]);
        }
        split2(sq, 0.f, ahi[8], alo[8]);
#pragma unroll
        for (int q = 9; q < 32; q++) { ahi[q] = 0u; alo[q] = 0u; }
        TCG_ST32(tb + 64 + woff, ahi);
        TCG_ST32(tb + 96 + 64 + woff, alo);
        TCG_WAIT_ST();
    }
    TCG_FENCE_BEFORE();
    __syncthreads();

    const uint64_t dW1h = mk_desc(smb + SO_W1HI);
    const uint64_t dW1l = mk_desc(smb + SO_W1LO);
    const uint64_t dW2h = mk_desc(smb + SO_W2HI);
    const uint64_t dW2l = mk_desc(smb + SO_W2LO);
    const uint64_t dWch = mk_desc(smb + SO_WC1HI);
    const uint64_t dWcl = mk_desc(smb + SO_WC1LO);

    // GEMM1: D1(192) = A1 @ W1^T, K=192 (12 ksteps), 3 bf16 splits
    if (wid == 0) {
        TCG_FENCE_AFTER();
        if (elect_one_pred()) {
#pragma unroll
            for (int k = 0; k < 12; k++)
                mma_f16(tb + 192, tb + 8 * k, dW1h + (uint64_t)((k >> 2) * 512 + (k & 3) * 2), k > 0);
#pragma unroll
            for (int k = 0; k < 12; k++)
                mma_f16(tb + 192, tb + 8 * k, dW1l + (uint64_t)((k >> 2) * 512 + (k & 3) * 2), true);
#pragma unroll
            for (int k = 0; k < 12; k++)
                mma_f16(tb + 192, tb + 96 + 8 * k, dW1h + (uint64_t)((k >> 2) * 512 + (k & 3) * 2), true);
            TCG_COMMIT(smb + SO_MBAR);
        }
    }
    MBAR_WAIT(smb + SO_MBAR, 0);
    TCG_FENCE_AFTER();

    // epilogue 1: t = silu(D1 + b1); A2 = split(t) -> cols 0..63
    {
        uint32_t d0[32], d1[32];
        TCG_LD32(d0, tb + 192);
        TCG_LD32(d1, tb + 224);
        TCG_WAIT_LD();
        float t[64];
#pragma unroll
        for (int n = 0; n < 32; n++) t[n] = silu_f(__uint_as_float(d0[n]) + sB1[n]);
#pragma unroll
        for (int n = 0; n < 32; n++) t[32 + n] = silu_f(__uint_as_float(d1[n]) + sB1[32 + n]);
        uint32_t ahi[32], alo[32];
#pragma unroll
        for (int q = 0; q < 32; q++) split2(t[2 * q], t[2 * q + 1], ahi[q], alo[q]);
        TCG_ST32(tb + 0 + woff, ahi);
        TCG_ST32(tb + 32 + woff, alo);
        TCG_WAIT_ST();
    }
    TCG_FENCE_BEFORE();
    __syncthreads();

    // GEMM2: D2(64) = A2 @ W2^T, K=64
    if (wid == 0) {
        TCG_FENCE_AFTER();
        if (elect_one_pred()) {
#pragma unroll
            for (int k = 0; k < 4; k++) mma_f16(tb + 64, tb + 8 * k, dW2h + 2 * k, k > 0);
#pragma unroll
            for (int k = 0; k < 4; k++) mma_f16(tb + 64, tb + 8 * k, dW2l + 2 * k, true);
#pragma unroll
            for (int k = 0; k < 4; k++) mma_f16(tb + 64, tb + 32 + 8 * k, dW2h + 2 * k, true);
            TCG_COMMIT(smb + SO_MBAR);
        }
    }
    MBAR_WAIT(smb + SO_MBAR, 1);
    TCG_FENCE_AFTER();

    // epilogue 2: msg = silu(D2 + b2); atomics; A3 = split(msg) -> cols 128..191
    {
        uint32_t d0[32], d1[32];
        TCG_LD32(d0, tb + 64);
        TCG_LD32(d1, tb + 96);
        TCG_WAIT_LD();
        float t[64];
#pragma unroll
        for (int n = 0; n < 32; n++) t[n] = silu_f(__uint_as_float(d0[n]) + sB2[n]);
#pragma unroll
        for (int n = 0; n < 32; n++) t[32 + n] = silu_f(__uint_as_float(d1[n]) + sB2[32 + n]);
        float* msgp = (float*)g_accum_msg + (size_t)r * HD;
#pragma unroll
        for (int q = 0; q < 16; q++)
            red4(msgp + 4 * q, t[4 * q], t[4 * q + 1], t[4 * q + 2], t[4 * q + 3]);
        uint32_t ahi[32], alo[32];
#pragma unroll
        for (int q = 0; q < 32; q++) split2(t[2 * q], t[2 * q + 1], ahi[q], alo[q]);
        TCG_ST32(tb + 128 + woff, ahi);
        TCG_ST32(tb + 160 + woff, alo);
        TCG_WAIT_ST();
    }
    TCG_FENCE_BEFORE();
    __syncthreads();

    // GEMM3: D3(192) = A3 @ Wc1^T, K=64
    if (wid == 0) {
        TCG_FENCE_AFTER();
        if (elect_one_pred()) {
#pragma unroll
            for (int k = 0; k < 4; k++) mma_f16(tb + 192, tb + 128 + 8 * k, dWch + 2 * k, k > 0);
#pragma unroll
            for (int k = 0; k < 4; k++) mma_f16(tb + 192, tb + 128 + 8 * k, dWcl + 2 * k, true);
#pragma unroll
            for (int k = 0; k < 4; k++) mma_f16(tb + 192, tb + 160 + 8 * k, dWch + 2 * k, true);
            TCG_COMMIT(smb + SO_MBAR);
        }
    }
    MBAR_WAIT(smb + SO_MBAR, 0);
    TCG_FENCE_AFTER();

    // epilogue 3: csum = silu(D3 + bc1) . wc2 + bc2 ; force atomics
    {
        uint32_t d0[32], d1[32];
        TCG_LD32(d0, tb + 192);
        TCG_LD32(d1, tb + 224);
        TCG_WAIT_LD();
        float csum = __ldg(bc2);
#pragma unroll
        for (int n = 0; n < 32; n++) csum += silu_f(__uint_as_float(d0[n]) + sBc1[n]) * sWc2[n];
#pragma unroll
        for (int n = 0; n < 32; n++)
            csum += silu_f(__uint_as_float(d1[n]) + sBc1[32 + n]) * sWc2[32 + n];
        red4((float*)g_accum_f + (size_t)4 * r, rx * csum, ry * csum, rz * csum, 1.0f);
    }

    __syncthreads();
    if (tid == 0) MBAR_INVAL(smb + SO_MBAR);
    if (wid == 0) TCG_DEALLOC(tb, 256);

#else
    // ================= fp32x2 fallback (verbatim R7, 897.6 us) =================
    extern __shared__ uint8_t sm8[];
    float* smf = (float*)sm8;
    float* sW1 = smf;                  // [145][64]
    float* sW2 = smf + 9280;           // [64][64]
    float* sWc1 = smf + 13376;         // [64][64]
    float* sWc2 = smf + 17472;         // 64
    float* sB1 = smf + 17536;
    float* sB2 = smf + 17600;
    float* sBc1 = smf + 17664;
    float* tbuf = smf + 17728;         // [64][128]

    int tid = threadIdx.x;
    for (int i = tid; i < 9280; i += 128) sW1[i] = w1e[i];
    for (int i = tid; i < 4096; i += 128) sW2[i] = w2e[i];
    for (int i = tid; i < 4096; i += 128) sWc1[i] = wc1[i];
    if (tid < 64) {
        sWc2[tid] = wc2[tid];
        sB1[tid] = b1e[tid];
        sB2[tid] = b2e[tid];
        sBc1[tid] = bc1[tid];
    }
    __syncthreads();

    const int half = tid >> 6;
    const int j = tid & 63;
    const int hoff = half * 32;
    const int e0 = blockIdx.x * 128 + 2 * j;

    int2 rr = *(const int2*)(row + e0);
    int2 cc = *(const int2*)(col + e0);
    const int r0 = rr.x, r1 = rr.y;
    const int c0 = cc.x, c1 = cc.y;

    float rx0 = x[3 * r0] - x[3 * c0];
    float ry0 = x[3 * r0 + 1] - x[3 * c0 + 1];
    float rz0 = x[3 * r0 + 2] - x[3 * c0 + 2];
    float rx1 = x[3 * r1] - x[3 * c1];
    float ry1 = x[3 * r1 + 1] - x[3 * c1 + 1];
    float rz1 = x[3 * r1 + 2] - x[3 * c1 + 2];
    float sq0 = rx0 * rx0 + ry0 * ry0 + rz0 * rz0;
    float sq1 = rx1 * rx1 + ry1 * ry1 + rz1 * rz1;

    ull acc0[16], acc1[16];

    const float* W1 = sW1 + hoff;
    init_bias2(acc0, acc1, sB1 + hoff);
    gemm_row2(acc0, acc1, W1, pack2(sq0), pack2(sq1));
    {
        const float4* hr0 = (const float4*)(h + (size_t)r0 * HD);
        const float4* hr1 = (const float4*)(h + (size_t)r1 * HD);
#pragma unroll 2
        for (int k = 0; k < 16; k++)
            gemm4_2(acc0, acc1, W1 + (1 + 4 * k) * 64, __ldg(hr0 + k), __ldg(hr1 + k));
        const float4* hc0 = (const float4*)(h + (size_t)c0 * HD);
        const float4* hc1 = (const float4*)(h + (size_t)c1 * HD);
#pragma unroll 2
        for (int k = 0; k < 16; k++)
            gemm4_2(acc0, acc1, W1 + (65 + 4 * k) * 64, __ldg(hc0 + k), __ldg(hc1 + k));
        const float4* ef0 = (const float4*)(edge_fea + (size_t)e0 * 16);
        const float4* ef1 = (const float4*)(edge_fea + (size_t)(e0 + 1) * 16);
#pragma unroll 2
        for (int k = 0; k < 4; k++)
            gemm4_2(acc0, acc1, W1 + (129 + 4 * k) * 64, __ldg(ef0 + k), __ldg(ef1 + k));
    }
#pragma unroll
    for (int q = 0; q < 16; q++) {
        float a, b, c, d;
        unpack2(acc0[q], a, b);
        unpack2(acc1[q], c, d);
        int f = hoff + 2 * q;
        *(float2*)&tbuf[f * 128 + 2 * j] = make_float2(silu_f(a), silu_f(c));
        *(float2*)&tbuf[(f + 1) * 128 + 2 * j] = make_float2(silu_f(b), silu_f(d));
    }
    __syncthreads();

    init_bias2(acc0, acc1, sB2 + hoff);
#pragma unroll 2
    for (int i = 0; i < 64; i++) {
        float2 tv = *(const float2*)&tbuf[i * 128 + 2 * j];
        gemm_row2(acc0, acc1, sW2 + i * 64 + hoff, pack2(tv.x), pack2(tv.y));
    }
    __syncthreads();

    {
        float* msgp0 = (float*)g_accum_msg + (size_t)r0 * HD + hoff;
        float* msgp1 = (float*)g_accum_msg + (size_t)r1 * HD + hoff;
#pragma unroll
        for (int q = 0; q < 8; q++) {
            float a0v, a1v, a2v, a3v, b0v, b1v, b2v, b3v;
            unpack2(acc0[2 * q], a0v, a1v);
            unpack2(acc0[2 * q + 1], a2v, a3v);
            unpack2(acc1[2 * q], b0v, b1v);
            unpack2(acc1[2 * q + 1], b2v, b3v);
            a0v = silu_f(a0v); a1v = silu_f(a1v); a2v = silu_f(a2v); a3v = silu_f(a3v);
            b0v = silu_f(b0v); b1v = silu_f(b1v); b2v = silu_f(b2v); b3v = silu_f(b3v);
            int f = hoff + 4 * q;
            *(float2*)&tbuf[f * 128 + 2 * j] = make_float2(a0v, b0v);
            *(float2*)&tbuf[(f + 1) * 128 + 2 * j] = make_float2(a1v, b1v);
            *(float2*)&tbuf[(f + 2) * 128 + 2 * j] = make_float2(a2v, b2v);
            *(float2*)&tbuf[(f + 3) * 128 + 2 * j] = make_float2(a3v, b3v);
            red4(msgp0 + 4 * q, a0v, a1v, a2v, a3v);
            red4(msgp1 + 4 * q, b0v, b1v, b2v, b3v);
        }
    }
    __syncthreads();

    init_bias2(acc0, acc1, sBc1 + hoff);
#pragma unroll 2
    for (int i = 0; i < 64; i++) {
        float2 tv = *(const float2*)&tbuf[i * 128 + 2 * j];
        gemm_row2(acc0, acc1, sWc1 + i * 64 + hoff, pack2(tv.x), pack2(tv.y));
    }

    float p0 = 0.f, p1 = 0.f;
#pragma unroll
    for (int q = 0; q < 16; q++) {
        float a, b, c, d;
        unpack2(acc0[q], a, b);
        unpack2(acc1[q], c, d);
        float w0 = sWc2[hoff + 2 * q], w1v = sWc2[hoff + 2 * q + 1];
        p0 += silu_f(a) * w0 + silu_f(b) * w1v;
        p1 += silu_f(c) * w0 + silu_f(d) * w1v;
    }
    __syncthreads();
    tbuf[(2 * j) * 2 + half] = p0;
    tbuf[(2 * j + 1) * 2 + half] = p1;
    __syncthreads();

    int m = 2 * j + half;
    float csum = tbuf[m * 2] + tbuf[m * 2 + 1] + __ldg(bc2);
    float rxm = half ? rx1 : rx0;
    float rym = half ? ry1 : ry0;
    float rzm = half ? rz1 : rz0;
    int rm = half ? r1 : r0;
    red4((float*)g_accum_f + (size_t)4 * rm, rxm * csum, rym * csum, rzm * csum, 1.0f);
#endif
}

// ---------------- node kernel (fp32x2, unchanged) ----------------
#define NODE_SMEM_FLOATS (8192 + 4096 + 64 + 64 + 64 * 128)
#define NODE_SMEM_BYTES (NODE_SMEM_FLOATS * 4)

__global__ __launch_bounds__(128, 2) void node_kernel(
    const float* __restrict__ x, const float* __restrict__ h,
    const float* __restrict__ wn1, const float* __restrict__ bn1,
    const float* __restrict__ wn2, const float* __restrict__ bn2,
    float* __restrict__ out) {
    extern __shared__ float smf[];
    float* sWn1 = smf;
    float* sWn2 = smf + 8192;
    float* sBn1 = smf + 12288;
    float* sBn2 = smf + 12352;
    float* tbuf = smf + 12416;

    int tid = threadIdx.x;
    for (int i = tid; i < 8192; i += 128) sWn1[i] = wn1[i];
    for (int i = tid; i < 4096; i += 128) sWn2[i] = wn2[i];
    if (tid < 64) {
        sBn1[tid] = bn1[tid];
        sBn2[tid] = bn2[tid];
    }
    __syncthreads();

    int v = blockIdx.x * 128 + tid;
    if (v >= NN) return;

    ull accp[32];
    init_bias(accp, sBn1);
    const float4* hv = (const float4*)(h + (size_t)v * HD);
#pragma unroll 2
    for (int k = 0; k < 16; k++) gemm4(accp, sWn1 + (4 * k) * 64, __ldg(hv + k));
    const float4* mv = (const float4*)((const float*)g_accum_msg + (size_t)v * HD);
#pragma unroll 2
    for (int k = 0; k < 16; k++) gemm4(accp, sWn1 + (64 + 4 * k) * 64, __ldg(mv + k));

#pragma unroll
    for (int p = 0; p < 32; p++) {
        float lo, hi;
        unpack2(accp[p], lo, hi);
        tbuf[(2 * p) * 128 + tid] = silu_f(lo);
        tbuf[(2 * p + 1) * 128 + tid] = silu_f(hi);
    }

    init_bias(accp, sBn2);
#pragma unroll 2
    for (int i = 0; i < 64; i++) gemm_row(accp, sWn2 + i * 64, pack2(tbuf[i * 128 + tid]));

    float* out_h = out + (size_t)NN * 3;
#pragma unroll
    for (int p = 0; p < 16; p++) {
        float a0, a1, a2, a3;
        unpack2(accp[2 * p], a0, a1);
        unpack2(accp[2 * p + 1], a2, a3);
        *(float4*)(out_h + (size_t)v * HD + 4 * p) = make_float4(a0, a1, a2, a3);
    }

    float4 af = g_accum_f[v];
    float deg = fmaxf(af.w, 1.0f);
    float fx = fminf(fmaxf(af.x / deg, -100.f), 100.f);
    float fy = fminf(fmaxf(af.y / deg, -100.f), 100.f);
    float fz = fminf(fmaxf(af.z / deg, -100.f), 100.f);
    out[3 * v + 0] = x[3 * v + 0] + fx;
    out[3 * v + 1] = x[3 * v + 1] + fy;
    out[3 * v + 2] = x[3 * v + 2] + fz;
}

// ---------------- launch ----------------
extern "C" void kernel_launch(void* const* d_in, const int* in_sizes, int n_in,
                              void* d_out, int out_size) {
    const float* x = (const float*)d_in[0];
    const float* h = (const float*)d_in[1];
    const float* edge_fea = (const float*)d_in[2];
    const float* w1e = (const float*)d_in[3];
    const float* b1e = (const float*)d_in[4];
    const float* w2e = (const float*)d_in[5];
    const float* b2e = (const float*)d_in[6];
    const float* wc1 = (const float*)d_in[7];
    const float* bc1 = (const float*)d_in[8];
    const float* wc2 = (const float*)d_in[9];
    const float* bc2 = (const float*)d_in[10];
    const float* wn1 = (const float*)d_in[11];
    const float* bn1 = (const float*)d_in[12];
    const float* wn2 = (const float*)d_in[13];
    const float* bn2 = (const float*)d_in[14];
    const int* row = (const int*)d_in[15];
    const int* col = (const int*)d_in[16];
    float* out = (float*)d_out;

    cudaFuncSetAttribute(edge_kernel, cudaFuncAttributeMaxDynamicSharedMemorySize,
                         EDGE_SMEM_BYTES);
    cudaFuncSetAttribute(node_kernel, cudaFuncAttributeMaxDynamicSharedMemorySize,
                         NODE_SMEM_BYTES);

    zero_kernel<<<512, 256>>>();
    prep_kernel<<<64, 256>>>(w1e, w2e, wc1);
    edge_kernel<<<NB, 128, EDGE_SMEM_BYTES>>>(x, h, edge_fea, w1e, b1e, w2e, b2e,
                                              wc1, bc1, wc2, bc2, row, col);
    node_kernel<<<(NN + 127) / 128, 128, NODE_SMEM_BYTES>>>(x, h, wn1, bn1, wn2, bn2, out);
}

// round 13
// speedup vs baseline: 1.8968x; 1.4462x over previous
#include <cuda_runtime.h>
#include <cuda_bf16.h>
#include <cstdint>

#define NN 50000
#define MM 800000
#define HD 64
#define NB (MM / 128)
#define EDGE_GRID 296

// Does this compilation pass target the architecture-specific sm_103a feature set?
#if defined(__CUDA_ARCH__) && (defined(__CUDA_ARCH_FEAT_SM103_ALL) || \
    (defined(__CUDA_ARCH_SPECIFIC__) && (__CUDA_ARCH__ == 1030)))
#define EDGE_TC 1
#else
#define EDGE_TC 0
#endif

// ---------------- device scratch (allocation-free) ----------------
__device__ float4 g_accum_f[NN];            // {fx, fy, fz, deg}
__device__ float4 g_accum_msg[NN * 16];     // 64 floats / node

// Pre-swizzled bf16 weight images (exact SMEM layout; linear copy per block)
__device__ uint4 g_W1hi[1536];   // [64 n, 192 k] bf16, SW128 blocked atoms (24576 B)
__device__ uint4 g_W1lo[1536];
__device__ uint4 g_W2hi[512];    // [64, 64]  (8192 B)
__device__ uint4 g_W2lo[512];
__device__ uint4 g_Wc1hi[512];
__device__ uint4 g_Wc1lo[512];

// ---------------- shared helpers ----------------
typedef unsigned long long ull;
__device__ __forceinline__ ull pack2(float v) {
    ull r;
    asm("mov.b64 %0, {%1, %1};" : "=l"(r) : "f"(v));
    return r;
}
__device__ __forceinline__ void unpack2(ull a, float& lo, float& hi) {
    asm("mov.b64 {%0, %1}, %2;" : "=f"(lo), "=f"(hi) : "l"(a));
}
__device__ __forceinline__ void ffma2(ull& acc, ull a, ull b) {
    asm("fma.rn.f32x2 %0, %1, %2, %0;" : "+l"(acc) : "l"(a), "l"(b));
}
__device__ __forceinline__ float silu_f(float x) {
    return __fdividef(x, 1.0f + __expf(-x));
}
__device__ __forceinline__ void red4(float* p, float a, float b, float c, float d) {
    asm volatile("red.global.add.v4.f32 [%0], {%1,%2,%3,%4};"
                 :: "l"(p), "f"(a), "f"(b), "f"(c), "f"(d) : "memory");
}

// bf16 hi/lo split of a pair (low half of u32 = even-k element)
__device__ __forceinline__ void split2(float a, float b, uint32_t& hi, uint32_t& lo) {
    __nv_bfloat16 ha = __float2bfloat16(a), hb = __float2bfloat16(b);
    hi = (uint32_t)__bfloat16_as_ushort(ha) | ((uint32_t)__bfloat16_as_ushort(hb) << 16);
    float la = a - __bfloat162float(ha), lb = b - __bfloat162float(hb);
    lo = (uint32_t)__bfloat16_as_ushort(__float2bfloat16(la)) |
         ((uint32_t)__bfloat16_as_ushort(__float2bfloat16(lb)) << 16);
}

// swizzled byte offset inside a B weight image [64 rows(n), K cols] blocked-atom SW128
__device__ __forceinline__ uint32_t boff(int n, int k) {
    uint32_t atom = (uint32_t)((k >> 6) * 8 + (n >> 3));
    uint32_t b = atom * 1024u + (uint32_t)(n & 7) * 128u + (uint32_t)(k & 63) * 2u;
    return b ^ ((b >> 3) & 0x70);
}

// ---------------- fp32x2 GEMV helpers (fallback edge + node kernel) ----------------
__device__ __forceinline__ void gemm_row2(ull* a0, ull* a1, const float* wrowhalf,
                                          ull v0, ull v1) {
    const ulonglong2* wr = (const ulonglong2*)wrowhalf;
#pragma unroll
    for (int q = 0; q < 8; q++) {
        ulonglong2 w = wr[q];
        ffma2(a0[2 * q], w.x, v0);
        ffma2(a0[2 * q + 1], w.y, v0);
        ffma2(a1[2 * q], w.x, v1);
        ffma2(a1[2 * q + 1], w.y, v1);
    }
}
__device__ __forceinline__ void gemm4_2(ull* a0, ull* a1, const float* wbase_half,
                                        float4 va, float4 vb) {
    gemm_row2(a0, a1, wbase_half, pack2(va.x), pack2(vb.x));
    gemm_row2(a0, a1, wbase_half + 64, pack2(va.y), pack2(vb.y));
    gemm_row2(a0, a1, wbase_half + 128, pack2(va.z), pack2(vb.z));
    gemm_row2(a0, a1, wbase_half + 192, pack2(va.w), pack2(vb.w));
}
__device__ __forceinline__ void init_bias2(ull* a0, ull* a1, const float* sBhalf) {
    const ulonglong2* bp = (const ulonglong2*)sBhalf;
#pragma unroll
    for (int q = 0; q < 8; q++) {
        ulonglong2 b = bp[q];
        a0[2 * q] = b.x;
        a0[2 * q + 1] = b.y;
        a1[2 * q] = b.x;
        a1[2 * q + 1] = b.y;
    }
}
__device__ __forceinline__ void gemm_row(ull* accp, const float* wrow, ull vv) {
    const ulonglong2* wr = (const ulonglong2*)wrow;
#pragma unroll
    for (int jj = 0; jj < 16; jj++) {
        ulonglong2 w = wr[jj];
        ffma2(accp[2 * jj], w.x, vv);
        ffma2(accp[2 * jj + 1], w.y, vv);
    }
}
__device__ __forceinline__ void gemm4(ull* accp, const float* wbase, float4 sv) {
    gemm_row(accp, wbase, pack2(sv.x));
    gemm_row(accp, wbase + 64, pack2(sv.y));
    gemm_row(accp, wbase + 128, pack2(sv.z));
    gemm_row(accp, wbase + 192, pack2(sv.w));
}
__device__ __forceinline__ void init_bias(ull* accp, const float* sB) {
    const ulonglong2* bp = (const ulonglong2*)sB;
#pragma unroll
    for (int q = 0; q < 16; q++) {
        ulonglong2 b = bp[q];
        accp[2 * q] = b.x;
        accp[2 * q + 1] = b.y;
    }
}

// ---------------- tcgen05 PTX helpers ----------------
__device__ __forceinline__ uint32_t smem_u32(const void* p) {
    uint32_t a;
    asm("{ .reg .u64 t; cvta.to.shared.u64 t, %1; cvt.u32.u64 %0, t; }" : "=r"(a) : "l"(p));
    return a;
}
__device__ __forceinline__ uint32_t elect_one_pred() {
    uint32_t p;
    asm volatile("{\n\t.reg .pred p;\n\telect.sync _|p, 0xFFFFFFFF;\n\tselp.b32 %0, 1, 0, p;\n\t}" : "=r"(p));
    return p;
}

#define TCG_ALLOC(sm, n)  asm volatile("tcgen05.alloc.cta_group::1.sync.aligned.shared::cta.b32 [%0], %1;" :: "r"((uint32_t)(sm)), "r"((uint32_t)(n)) : "memory")
#define TCG_DEALLOC(t, n) asm volatile("tcgen05.dealloc.cta_group::1.sync.aligned.b32 %0, %1;" :: "r"(t), "r"((uint32_t)(n)))
#define TCG_WAIT_ST()     asm volatile("tcgen05.wait::st.sync.aligned;" ::: "memory")
#define TCG_WAIT_LD()     asm volatile("tcgen05.wait::ld.sync.aligned;" ::: "memory")
#define TCG_FENCE_BEFORE() asm volatile("tcgen05.fence::before_thread_sync;" ::: "memory")
#define TCG_FENCE_AFTER()  asm volatile("tcgen05.fence::after_thread_sync;" ::: "memory")
#define TCG_COMMIT(mb)    asm volatile("tcgen05.commit.cta_group::1.mbarrier::arrive::one.shared::cluster.b64 [%0];" :: "r"((uint32_t)(mb)) : "memory")
#define MBAR_INIT(mb, n)  asm volatile("mbarrier.init.shared.b64 [%0], %1;" :: "r"((uint32_t)(mb)), "r"((uint32_t)(n)) : "memory")
#define MBAR_INVAL(mb)    asm volatile("mbarrier.inval.shared.b64 [%0];" :: "r"((uint32_t)(mb)) : "memory")

#define MBAR_WAIT(mb, par) do {                                                      \
    uint32_t _m = (uint32_t)(mb), _p = (uint32_t)(par), _d;                          \
    asm volatile("{\n\t.reg .pred p;\n\t"                                            \
        "mbarrier.try_wait.parity.acquire.cta.shared::cta.b64 p, [%1], %2;\n\t"      \
        "selp.b32 %0, 1, 0, p;\n\t}" : "=r"(_d) : "r"(_m), "r"(_p) : "memory");      \
    if (!_d) {                                                                       \
        asm volatile("{\n\t.reg .pred P1;\n\t"                                       \
            "WL_%=:\n\t"                                                             \
            "mbarrier.try_wait.parity.acquire.cta.shared::cta.b64 P1, [%0], %1, 0x989680;\n\t" \
            "@P1 bra.uni WD_%=;\n\tbra.uni WL_%=;\n\tWD_%=:\n\t}"                    \
            :: "r"(_m), "r"(_p) : "memory");                                         \
    }                                                                                \
} while (0)

#define TCG_ST32(addr, r)                                                            \
    asm volatile("tcgen05.st.sync.aligned.32x32b.x32.b32 [%0], "                     \
        "{%1, %2, %3, %4, %5, %6, %7, %8, %9, %10, %11, %12, %13, %14, %15, %16, "   \
        " %17, %18, %19, %20, %21, %22, %23, %24, %25, %26, %27, %28, %29, %30, %31, %32};" \
        :: "r"(addr),                                                                \
           "r"((r)[0]), "r"((r)[1]), "r"((r)[2]), "r"((r)[3]),                       \
           "r"((r)[4]), "r"((r)[5]), "r"((r)[6]), "r"((r)[7]),                       \
           "r"((r)[8]), "r"((r)[9]), "r"((r)[10]), "r"((r)[11]),                     \
           "r"((r)[12]), "r"((r)[13]), "r"((r)[14]), "r"((r)[15]),                   \
           "r"((r)[16]), "r"((r)[17]), "r"((r)[18]), "r"((r)[19]),                   \
           "r"((r)[20]), "r"((r)[21]), "r"((r)[22]), "r"((r)[23]),                   \
           "r"((r)[24]), "r"((r)[25]), "r"((r)[26]), "r"((r)[27]),                   \
           "r"((r)[28]), "r"((r)[29]), "r"((r)[30]), "r"((r)[31]) : "memory")

#define TCG_LD32(r, addr)                                                            \
    asm volatile("tcgen05.ld.sync.aligned.32x32b.x32.b32 "                           \
        "{%0, %1, %2, %3, %4, %5, %6, %7, %8, %9, %10, %11, %12, %13, %14, %15, "    \
        " %16, %17, %18, %19, %20, %21, %22, %23, %24, %25, %26, %27, %28, %29, %30, %31}, [%32];" \
        : "=r"((r)[0]), "=r"((r)[1]), "=r"((r)[2]), "=r"((r)[3]),                    \
          "=r"((r)[4]), "=r"((r)[5]), "=r"((r)[6]), "=r"((r)[7]),                    \
          "=r"((r)[8]), "=r"((r)[9]), "=r"((r)[10]), "=r"((r)[11]),                  \
          "=r"((r)[12]), "=r"((r)[13]), "=r"((r)[14]), "=r"((r)[15]),                \
          "=r"((r)[16]), "=r"((r)[17]), "=r"((r)[18]), "=r"((r)[19]),                \
          "=r"((r)[20]), "=r"((r)[21]), "=r"((r)[22]), "=r"((r)[23]),                \
          "=r"((r)[24]), "=r"((r)[25]), "=r"((r)[26]), "=r"((r)[27]),                \
          "=r"((r)[28]), "=r"((r)[29]), "=r"((r)[30]), "=r"((r)[31])                 \
        : "r"(addr))

// idesc kind::f16: F32 dtype, BF16 a/b, N=64 (8<<17), M=128 (8<<24)
#define IDESC_F16 0x8100490u

#if EDGE_TC
__device__ __forceinline__ void mma_f16(uint32_t d, uint32_t a, uint64_t bdesc, bool acc) {
    uint32_t en = acc ? 1u : 0u, z = 0u;
    asm volatile("{\n\t.reg .pred p;\n\tsetp.ne.u32 p, %4, 0;\n\t"
        "tcgen05.mma.cta_group::1.kind::f16 [%0], [%1], %2, %3, {%5, %5, %5, %5}, p;\n\t}"
        :: "r"(d), "r"(a), "l"(bdesc), "r"(IDESC_F16), "r"(en), "r"(z) : "memory");
}
#endif

// SW128 K-major descriptor base (LBO=1, SBO=64, version 1)
static constexpr uint64_t DESC_BASE_SW128 =
    (uint64_t(2) << 61) | (uint64_t(1) << 46) | (uint64_t(64) << 32) | (uint64_t(1) << 16);
__device__ __forceinline__ uint64_t mk_desc(uint32_t addr) {
    return DESC_BASE_SW128 | ((uint64_t)(addr >> 4) & 0x3FFF);
}

// ---------------- zero scratch ----------------
__global__ void zero_kernel() {
    int i = blockIdx.x * blockDim.x + threadIdx.x;
    int stride = gridDim.x * blockDim.x;
    const float4 z = make_float4(0.f, 0.f, 0.f, 0.f);
    for (int k = i; k < NN; k += stride) g_accum_f[k] = z;
    for (int k = i; k < NN * 16; k += stride) g_accum_msg[k] = z;
}

// ---------------- weight prep: transpose + bf16 split + swizzle ----------------
__global__ void prep_kernel(const float* __restrict__ w1e, const float* __restrict__ w2e,
                            const float* __restrict__ wc1) {
    int i = blockIdx.x * blockDim.x + threadIdx.x;
    int stride = gridDim.x * blockDim.x;
    uint8_t* w1h = (uint8_t*)g_W1hi; uint8_t* w1l = (uint8_t*)g_W1lo;
    uint8_t* w2h = (uint8_t*)g_W2hi; uint8_t* w2l = (uint8_t*)g_W2lo;
    uint8_t* wch = (uint8_t*)g_Wc1hi; uint8_t* wcl = (uint8_t*)g_Wc1lo;
    for (int idx = i; idx < 64 * 192; idx += stride) {
        int n = idx / 192, k = idx % 192;
        float f = 0.f;
        if (k <= 143) f = w1e[(1 + k) * 64 + n];
        else if (k == 144) f = w1e[n];
        __nv_bfloat16 h = __float2bfloat16(f);
        float lo = f - __bfloat162float(h);
        uint32_t o = boff(n, k);
        *(__nv_bfloat16*)(w1h + o) = h;
        *(__nv_bfloat16*)(w1l + o) = __float2bfloat16(lo);
    }
    for (int idx = i; idx < 64 * 64; idx += stride) {
        int n = idx / 64, k = idx % 64;
        uint32_t o = boff(n, k);
        float f = w2e[k * 64 + n];
        __nv_bfloat16 h = __float2bfloat16(f);
        *(__nv_bfloat16*)(w2h + o) = h;
        *(__nv_bfloat16*)(w2l + o) = __float2bfloat16(f - __bfloat162float(h));
        float g = wc1[k * 64 + n];
        __nv_bfloat16 hg = __float2bfloat16(g);
        *(__nv_bfloat16*)(wch + o) = hg;
        *(__nv_bfloat16*)(wcl + o) = __float2bfloat16(g - __bfloat162float(hg));
    }
}

// ---------------- edge kernel: PERSISTENT tcgen05 or fp32x2 fallback ----------------
#define SO_TMEM 0
#define SO_MBAR 8
#define SO_B1   16
#define SO_B2   272
#define SO_BC1  528
#define SO_WC2  784
#define SO_W1HI 4096
#define SO_W1LO 28672
#define SO_W2HI 53248
#define SO_W2LO 61440
#define SO_WC1HI 69632
#define SO_WC1LO 77824
#define EDGE_SMEM_BYTES ((9280 + 4096 + 4096 + 4 * 64 + 64 * 128) * 4)   // 103680 >= 86016

__global__ __launch_bounds__(128, 2) void edge_kernel(
    const float* __restrict__ x, const float* __restrict__ h,
    const float* __restrict__ edge_fea,
    const float* __restrict__ w1e, const float* __restrict__ b1e,
    const float* __restrict__ w2e, const float* __restrict__ b2e,
    const float* __restrict__ wc1, const float* __restrict__ bc1,
    const float* __restrict__ wc2, const float* __restrict__ bc2,
    const int* __restrict__ row, const int* __restrict__ col) {
#if EDGE_TC
    // ================= persistent tcgen05 path =================
    extern __shared__ uint8_t sm[];
    const uint32_t smb = smem_u32(sm);
    const int tid = threadIdx.x;
    const int wid = tid >> 5;
    const uint32_t woff = (uint32_t)wid << 21;

    // one-time staging
    {
        uint4* d;
        d = (uint4*)(sm + SO_W1HI);
        for (int i = tid; i < 1536; i += 128) d[i] = g_W1hi[i];
        d = (uint4*)(sm + SO_W1LO);
        for (int i = tid; i < 1536; i += 128) d[i] = g_W1lo[i];
        d = (uint4*)(sm + SO_W2HI);
        for (int i = tid; i < 512; i += 128) d[i] = g_W2hi[i];
        d = (uint4*)(sm + SO_W2LO);
        for (int i = tid; i < 512; i += 128) d[i] = g_W2lo[i];
        d = (uint4*)(sm + SO_WC1HI);
        for (int i = tid; i < 512; i += 128) d[i] = g_Wc1hi[i];
        d = (uint4*)(sm + SO_WC1LO);
        for (int i = tid; i < 512; i += 128) d[i] = g_Wc1lo[i];
    }
    float* sB1 = (float*)(sm + SO_B1);
    float* sB2 = (float*)(sm + SO_B2);
    float* sBc1 = (float*)(sm + SO_BC1);
    float* sWc2 = (float*)(sm + SO_WC2);
    if (tid < 64) {
        sB1[tid] = b1e[tid];
        sB2[tid] = b2e[tid];
        sBc1[tid] = bc1[tid];
        sWc2[tid] = wc2[tid];
    }
    if (wid == 0) TCG_ALLOC(smb + SO_TMEM, 256);
    if (tid == 0) MBAR_INIT(smb + SO_MBAR, 1);
    __syncthreads();
    uint32_t tb;
    asm volatile("ld.shared.b32 %0, [%1];" : "=r"(tb) : "r"(smb + SO_TMEM));

    const uint64_t dW1h = mk_desc(smb + SO_W1HI);
    const uint64_t dW1l = mk_desc(smb + SO_W1LO);
    const uint64_t dW2h = mk_desc(smb + SO_W2HI);
    const uint64_t dW2l = mk_desc(smb + SO_W2LO);
    const uint64_t dWch = mk_desc(smb + SO_WC1HI);
    const uint64_t dWcl = mk_desc(smb + SO_WC1LO);
    const float bc2v = __ldg(bc2);

    uint32_t wp = 0;   // running mbarrier wait counter (parity = wp & 1)

    for (int t = blockIdx.x; t < NB; t += EDGE_GRID) {
        const int e = t * 128 + tid;
        const int r = row[e], c = col[e];
        const float rx = x[3 * r] - x[3 * c];
        const float ry = x[3 * r + 1] - x[3 * c + 1];
        const float rz = x[3 * r + 2] - x[3 * c + 2];
        const float sq = rx * rx + ry * ry + rz * rz;

        // ---- A1 build (TMEM cols 0..191; disjoint from D3 192..255 of prev tile) ----
        {
            uint32_t ahi[32], alo[32];
            const float4* hr = (const float4*)(h + (size_t)r * HD);
#pragma unroll
            for (int q = 0; q < 16; q++) {
                float4 v = __ldg(hr + q);
                split2(v.x, v.y, ahi[2 * q], alo[2 * q]);
                split2(v.z, v.w, ahi[2 * q + 1], alo[2 * q + 1]);
            }
            TCG_ST32(tb + 0 + woff, ahi);
            TCG_ST32(tb + 96 + woff, alo);
            const float4* hc = (const float4*)(h + (size_t)c * HD);
#pragma unroll
            for (int q = 0; q < 16; q++) {
                float4 v = __ldg(hc + q);
                split2(v.x, v.y, ahi[2 * q], alo[2 * q]);
                split2(v.z, v.w, ahi[2 * q + 1], alo[2 * q + 1]);
            }
            TCG_ST32(tb + 32 + woff, ahi);
            TCG_ST32(tb + 96 + 32 + woff, alo);
            const float4* ef = (const float4*)(edge_fea + (size_t)e * 16);
#pragma unroll
            for (int q = 0; q < 4; q++) {
                float4 v = __ldg(ef + q);
                split2(v.x, v.y, ahi[2 * q], alo[2 * q]);
                split2(v.z, v.w, ahi[2 * q + 1], alo[2 * q + 1]);
            }
            split2(sq, 0.f, ahi[8], alo[8]);
#pragma unroll
            for (int q = 9; q < 32; q++) { ahi[q] = 0u; alo[q] = 0u; }
            TCG_ST32(tb + 64 + woff, ahi);
            TCG_ST32(tb + 96 + 64 + woff, alo);
            TCG_WAIT_ST();
        }
        TCG_FENCE_BEFORE();
        __syncthreads();

        // ---- GEMM1: D1(192) = A1 @ W1^T, K=192, 3 bf16 splits ----
        if (wid == 0) {
            TCG_FENCE_AFTER();
            if (elect_one_pred()) {
#pragma unroll
                for (int k = 0; k < 12; k++)
                    mma_f16(tb + 192, tb + 8 * k, dW1h + (uint64_t)((k >> 2) * 512 + (k & 3) * 2), k > 0);
#pragma unroll
                for (int k = 0; k < 12; k++)
                    mma_f16(tb + 192, tb + 8 * k, dW1l + (uint64_t)((k >> 2) * 512 + (k & 3) * 2), true);
#pragma unroll
                for (int k = 0; k < 12; k++)
                    mma_f16(tb + 192, tb + 96 + 8 * k, dW1h + (uint64_t)((k >> 2) * 512 + (k & 3) * 2), true);
                TCG_COMMIT(smb + SO_MBAR);
            }
        }
        MBAR_WAIT(smb + SO_MBAR, wp & 1);
        wp++;
        TCG_FENCE_AFTER();

        // ---- epilogue 1: t1 = silu(D1 + b1); A2 = split(t1) -> cols 0..63 ----
        {
            uint32_t d0[32], d1[32];
            TCG_LD32(d0, tb + 192);
            TCG_LD32(d1, tb + 224);
            TCG_WAIT_LD();
            float tt[64];
#pragma unroll
            for (int n = 0; n < 32; n++) tt[n] = silu_f(__uint_as_float(d0[n]) + sB1[n]);
#pragma unroll
            for (int n = 0; n < 32; n++) tt[32 + n] = silu_f(__uint_as_float(d1[n]) + sB1[32 + n]);
            uint32_t ahi[32], alo[32];
#pragma unroll
            for (int q = 0; q < 32; q++) split2(tt[2 * q], tt[2 * q + 1], ahi[q], alo[q]);
            TCG_ST32(tb + 0 + woff, ahi);
            TCG_ST32(tb + 32 + woff, alo);
            TCG_WAIT_ST();
        }
        TCG_FENCE_BEFORE();
        __syncthreads();

        // ---- GEMM2: D2(64) = A2 @ W2^T, K=64 ----
        if (wid == 0) {
            TCG_FENCE_AFTER();
            if (elect_one_pred()) {
#pragma unroll
                for (int k = 0; k < 4; k++) mma_f16(tb + 64, tb + 8 * k, dW2h + 2 * k, k > 0);
#pragma unroll
                for (int k = 0; k < 4; k++) mma_f16(tb + 64, tb + 8 * k, dW2l + 2 * k, true);
#pragma unroll
                for (int k = 0; k < 4; k++) mma_f16(tb + 64, tb + 32 + 8 * k, dW2h + 2 * k, true);
                TCG_COMMIT(smb + SO_MBAR);
            }
        }
        MBAR_WAIT(smb + SO_MBAR, wp & 1);
        wp++;
        TCG_FENCE_AFTER();

        // ---- epilogue 2: msg = silu(D2 + b2); atomics; A3 = split(msg) -> cols 128..191 ----
        {
            uint32_t d0[32], d1[32];
            TCG_LD32(d0, tb + 64);
            TCG_LD32(d1, tb + 96);
            TCG_WAIT_LD();
            float tt[64];
#pragma unroll
            for (int n = 0; n < 32; n++) tt[n] = silu_f(__uint_as_float(d0[n]) + sB2[n]);
#pragma unroll
            for (int n = 0; n < 32; n++) tt[32 + n] = silu_f(__uint_as_float(d1[n]) + sB2[32 + n]);
            float* msgp = (float*)g_accum_msg + (size_t)r * HD;
#pragma unroll
            for (int q = 0; q < 16; q++)
                red4(msgp + 4 * q, tt[4 * q], tt[4 * q + 1], tt[4 * q + 2], tt[4 * q + 3]);
            uint32_t ahi[32], alo[32];
#pragma unroll
            for (int q = 0; q < 32; q++) split2(tt[2 * q], tt[2 * q + 1], ahi[q], alo[q]);
            TCG_ST32(tb + 128 + woff, ahi);
            TCG_ST32(tb + 160 + woff, alo);
            TCG_WAIT_ST();
        }
        TCG_FENCE_BEFORE();
        __syncthreads();

        // ---- GEMM3: D3(192) = A3 @ Wc1^T, K=64 ----
        if (wid == 0) {
            TCG_FENCE_AFTER();
            if (elect_one_pred()) {
#pragma unroll
                for (int k = 0; k < 4; k++) mma_f16(tb + 192, tb + 128 + 8 * k, dWch + 2 * k, k > 0);
#pragma unroll
                for (int k = 0; k < 4; k++) mma_f16(tb + 192, tb + 128 + 8 * k, dWcl + 2 * k, true);
#pragma unroll
                for (int k = 0; k < 4; k++) mma_f16(tb + 192, tb + 160 + 8 * k, dWch + 2 * k, true);
                TCG_COMMIT(smb + SO_MBAR);
            }
        }
        MBAR_WAIT(smb + SO_MBAR, wp & 1);
        wp++;
        TCG_FENCE_AFTER();

        // ---- epilogue 3: csum = silu(D3 + bc1) . wc2 + bc2 ; force atomics ----
        {
            uint32_t d0[32], d1[32];
            TCG_LD32(d0, tb + 192);
            TCG_LD32(d1, tb + 224);
            TCG_WAIT_LD();
            float csum = bc2v;
#pragma unroll
            for (int n = 0; n < 32; n++) csum += silu_f(__uint_as_float(d0[n]) + sBc1[n]) * sWc2[n];
#pragma unroll
            for (int n = 0; n < 32; n++)
                csum += silu_f(__uint_as_float(d1[n]) + sBc1[32 + n]) * sWc2[32 + n];
            red4((float*)g_accum_f + (size_t)4 * r, rx * csum, ry * csum, rz * csum, 1.0f);
        }
        __syncthreads();   // all warps done with D3 reads before next tile's A-build
    }

    if (tid == 0) MBAR_INVAL(smb + SO_MBAR);
    __syncthreads();
    if (wid == 0) TCG_DEALLOC(tb, 256);

#else
    // ================= persistent fp32x2 fallback =================
    extern __shared__ uint8_t sm8[];
    float* smf = (float*)sm8;
    float* sW1 = smf;                  // [145][64]
    float* sW2 = smf + 9280;           // [64][64]
    float* sWc1 = smf + 13376;         // [64][64]
    float* sWc2 = smf + 17472;         // 64
    float* sB1 = smf + 17536;
    float* sB2 = smf + 17600;
    float* sBc1 = smf + 17664;
    float* tbuf = smf + 17728;         // [64][128]

    int tid = threadIdx.x;
    for (int i = tid; i < 9280; i += 128) sW1[i] = w1e[i];
    for (int i = tid; i < 4096; i += 128) sW2[i] = w2e[i];
    for (int i = tid; i < 4096; i += 128) sWc1[i] = wc1[i];
    if (tid < 64) {
        sWc2[tid] = wc2[tid];
        sB1[tid] = b1e[tid];
        sB2[tid] = b2e[tid];
        sBc1[tid] = bc1[tid];
    }
    __syncthreads();

    const int half = tid >> 6;
    const int j = tid & 63;
    const int hoff = half * 32;
    const float bc2v = __ldg(bc2);

    for (int t = blockIdx.x; t < NB; t += EDGE_GRID) {
        __syncthreads();   // close prior tile's tbuf reuse window
        const int e0 = t * 128 + 2 * j;

        int2 rr = *(const int2*)(row + e0);
        int2 cc = *(const int2*)(col + e0);
        const int r0 = rr.x, r1 = rr.y;
        const int c0 = cc.x, c1 = cc.y;

        float rx0 = x[3 * r0] - x[3 * c0];
        float ry0 = x[3 * r0 + 1] - x[3 * c0 + 1];
        float rz0 = x[3 * r0 + 2] - x[3 * c0 + 2];
        float rx1 = x[3 * r1] - x[3 * c1];
        float ry1 = x[3 * r1 + 1] - x[3 * c1 + 1];
        float rz1 = x[3 * r1 + 2] - x[3 * c1 + 2];
        float sq0 = rx0 * rx0 + ry0 * ry0 + rz0 * rz0;
        float sq1 = rx1 * rx1 + ry1 * ry1 + rz1 * rz1;

        ull acc0[16], acc1[16];

        const float* W1 = sW1 + hoff;
        init_bias2(acc0, acc1, sB1 + hoff);
        gemm_row2(acc0, acc1, W1, pack2(sq0), pack2(sq1));
        {
            const float4* hr0 = (const float4*)(h + (size_t)r0 * HD);
            const float4* hr1 = (const float4*)(h + (size_t)r1 * HD);
#pragma unroll 2
            for (int k = 0; k < 16; k++)
                gemm4_2(acc0, acc1, W1 + (1 + 4 * k) * 64, __ldg(hr0 + k), __ldg(hr1 + k));
            const float4* hc0 = (const float4*)(h + (size_t)c0 * HD);
            const float4* hc1 = (const float4*)(h + (size_t)c1 * HD);
#pragma unroll 2
            for (int k = 0; k < 16; k++)
                gemm4_2(acc0, acc1, W1 + (65 + 4 * k) * 64, __ldg(hc0 + k), __ldg(hc1 + k));
            const float4* ef0 = (const float4*)(edge_fea + (size_t)e0 * 16);
            const float4* ef1 = (const float4*)(edge_fea + (size_t)(e0 + 1) * 16);
#pragma unroll 2
            for (int k = 0; k < 4; k++)
                gemm4_2(acc0, acc1, W1 + (129 + 4 * k) * 64, __ldg(ef0 + k), __ldg(ef1 + k));
        }
#pragma unroll
        for (int q = 0; q < 16; q++) {
            float a, b, c, d;
            unpack2(acc0[q], a, b);
            unpack2(acc1[q], c, d);
            int f = hoff + 2 * q;
            *(float2*)&tbuf[f * 128 + 2 * j] = make_float2(silu_f(a), silu_f(c));
            *(float2*)&tbuf[(f + 1) * 128 + 2 * j] = make_float2(silu_f(b), silu_f(d));
        }
        __syncthreads();

        init_bias2(acc0, acc1, sB2 + hoff);
#pragma unroll 2
        for (int i = 0; i < 64; i++) {
            float2 tv = *(const float2*)&tbuf[i * 128 + 2 * j];
            gemm_row2(acc0, acc1, sW2 + i * 64 + hoff, pack2(tv.x), pack2(tv.y));
        }
        __syncthreads();

        {
            float* msgp0 = (float*)g_accum_msg + (size_t)r0 * HD + hoff;
            float* msgp1 = (float*)g_accum_msg + (size_t)r1 * HD + hoff;
#pragma unroll
            for (int q = 0; q < 8; q++) {
                float a0v, a1v, a2v, a3v, b0v, b1v, b2v, b3v;
                unpack2(acc0[2 * q], a0v, a1v);
                unpack2(acc0[2 * q + 1], a2v, a3v);
                unpack2(acc1[2 * q], b0v, b1v);
                unpack2(acc1[2 * q + 1], b2v, b3v);
                a0v = silu_f(a0v); a1v = silu_f(a1v); a2v = silu_f(a2v); a3v = silu_f(a3v);
                b0v = silu_f(b0v); b1v = silu_f(b1v); b2v = silu_f(b2v); b3v = silu_f(b3v);
                int f = hoff + 4 * q;
                *(float2*)&tbuf[f * 128 + 2 * j] = make_float2(a0v, b0v);
                *(float2*)&tbuf[(f + 1) * 128 + 2 * j] = make_float2(a1v, b1v);
                *(float2*)&tbuf[(f + 2) * 128 + 2 * j] = make_float2(a2v, b2v);
                *(float2*)&tbuf[(f + 3) * 128 + 2 * j] = make_float2(a3v, b3v);
                red4(msgp0 + 4 * q, a0v, a1v, a2v, a3v);
                red4(msgp1 + 4 * q, b0v, b1v, b2v, b3v);
            }
        }
        __syncthreads();

        init_bias2(acc0, acc1, sBc1 + hoff);
#pragma unroll 2
        for (int i = 0; i < 64; i++) {
            float2 tv = *(const float2*)&tbuf[i * 128 + 2 * j];
            gemm_row2(acc0, acc1, sWc1 + i * 64 + hoff, pack2(tv.x), pack2(tv.y));
        }

        float p0 = 0.f, p1 = 0.f;
#pragma unroll
        for (int q = 0; q < 16; q++) {
            float a, b, c, d;
            unpack2(acc0[q], a, b);
            unpack2(acc1[q], c, d);
            float w0 = sWc2[hoff + 2 * q], w1v = sWc2[hoff + 2 * q + 1];
            p0 += silu_f(a) * w0 + silu_f(b) * w1v;
            p1 += silu_f(c) * w0 + silu_f(d) * w1v;
        }
        __syncthreads();
        tbuf[(2 * j) * 2 + half] = p0;
        tbuf[(2 * j + 1) * 2 + half] = p1;
        __syncthreads();

        int m = 2 * j + half;
        float csum = tbuf[m * 2] + tbuf[m * 2 + 1] + bc2v;
        float rxm = half ? rx1 : rx0;
        float rym = half ? ry1 : ry0;
        float rzm = half ? rz1 : rz0;
        int rm = half ? r1 : r0;
        red4((float*)g_accum_f + (size_t)4 * rm, rxm * csum, rym * csum, rzm * csum, 1.0f);
    }
#endif
}

// ---------------- node kernel (fp32x2, unchanged) ----------------
#define NODE_SMEM_FLOATS (8192 + 4096 + 64 + 64 + 64 * 128)
#define NODE_SMEM_BYTES (NODE_SMEM_FLOATS * 4)

__global__ __launch_bounds__(128, 2) void node_kernel(
    const float* __restrict__ x, const float* __restrict__ h,
    const float* __restrict__ wn1, const float* __restrict__ bn1,
    const float* __restrict__ wn2, const float* __restrict__ bn2,
    float* __restrict__ out) {
    extern __shared__ float smf[];
    float* sWn1 = smf;
    float* sWn2 = smf + 8192;
    float* sBn1 = smf + 12288;
    float* sBn2 = smf + 12352;
    float* tbuf = smf + 12416;

    int tid = threadIdx.x;
    for (int i = tid; i < 8192; i += 128) sWn1[i] = wn1[i];
    for (int i = tid; i < 4096; i += 128) sWn2[i] = wn2[i];
    if (tid < 64) {
        sBn1[tid] = bn1[tid];
        sBn2[tid] = bn2[tid];
    }
    __syncthreads();

    int v = blockIdx.x * 128 + tid;
    if (v >= NN) return;

    ull accp[32];
    init_bias(accp, sBn1);
    const float4* hv = (const float4*)(h + (size_t)v * HD);
#pragma unroll 2
    for (int k = 0; k < 16; k++) gemm4(accp, sWn1 + (4 * k) * 64, __ldg(hv + k));
    const float4* mv = (const float4*)((const float*)g_accum_msg + (size_t)v * HD);
#pragma unroll 2
    for (int k = 0; k < 16; k++) gemm4(accp, sWn1 + (64 + 4 * k) * 64, __ldg(mv + k));

#pragma unroll
    for (int p = 0; p < 32; p++) {
        float lo, hi;
        unpack2(accp[p], lo, hi);
        tbuf[(2 * p) * 128 + tid] = silu_f(lo);
        tbuf[(2 * p + 1) * 128 + tid] = silu_f(hi);
    }

    init_bias(accp, sBn2);
#pragma unroll 2
    for (int i = 0; i < 64; i++) gemm_row(accp, sWn2 + i * 64, pack2(tbuf[i * 128 + tid]));

    float* out_h = out + (size_t)NN * 3;
#pragma unroll
    for (int p = 0; p < 16; p++) {
        float a0, a1, a2, a3;
        unpack2(accp[2 * p], a0, a1);
        unpack2(accp[2 * p + 1], a2, a3);
        *(float4*)(out_h + (size_t)v * HD + 4 * p) = make_float4(a0, a1, a2, a3);
    }

    float4 af = g_accum_f[v];
    float deg = fmaxf(af.w, 1.0f);
    float fx = fminf(fmaxf(af.x / deg, -100.f), 100.f);
    float fy = fminf(fmaxf(af.y / deg, -100.f), 100.f);
    float fz = fminf(fmaxf(af.z / deg, -100.f), 100.f);
    out[3 * v + 0] = x[3 * v + 0] + fx;
    out[3 * v + 1] = x[3 * v + 1] + fy;
    out[3 * v + 2] = x[3 * v + 2] + fz;
}

// ---------------- launch ----------------
extern "C" void kernel_launch(void* const* d_in, const int* in_sizes, int n_in,
                              void* d_out, int out_size) {
    const float* x = (const float*)d_in[0];
    const float* h = (const float*)d_in[1];
    const float* edge_fea = (const float*)d_in[2];
    const float* w1e = (const float*)d_in[3];
    const float* b1e = (const float*)d_in[4];
    const float* w2e = (const float*)d_in[5];
    const float* b2e = (const float*)d_in[6];
    const float* wc1 = (const float*)d_in[7];
    const float* bc1 = (const float*)d_in[8];
    const float* wc2 = (const float*)d_in[9];
    const float* bc2 = (const float*)d_in[10];
    const float* wn1 = (const float*)d_in[11];
    const float* bn1 = (const float*)d_in[12];
    const float* wn2 = (const float*)d_in[13];
    const float* bn2 = (const float*)d_in[14];
    const int* row = (const int*)d_in[15];
    const int* col = (const int*)d_in[16];
    float* out = (float*)d_out;

    cudaFuncSetAttribute(edge_kernel, cudaFuncAttributeMaxDynamicSharedMemorySize,
                         EDGE_SMEM_BYTES);
    cudaFuncSetAttribute(node_kernel, cudaFuncAttributeMaxDynamicSharedMemorySize,
                         NODE_SMEM_BYTES);

    zero_kernel<<<512, 256>>>();
    prep_kernel<<<64, 256>>>(w1e, w2e, wc1);
    edge_kernel<<<EDGE_GRID, 128, EDGE_SMEM_BYTES>>>(x, h, edge_fea, w1e, b1e, w2e, b2e,
                                                     wc1, bc1, wc2, bc2, row, col);
    node_kernel<<<(NN + 127) / 128, 128, NODE_SMEM_BYTES>>>(x, h, wn1, bn1, wn2, bn2, out);
}

// round 16
// speedup vs baseline: 2.2736x; 1.1986x over previous
#include <cuda_runtime.h>
#include <cuda_bf16.h>
#include <cstdint>

#define NN 50000
#define MM 800000
#define HD 64
#define NB (MM / 128)
#define EDGE_GRID 296

// Does this compilation pass target the architecture-specific sm_103a feature set?
#if defined(__CUDA_ARCH__) && (defined(__CUDA_ARCH_FEAT_SM103_ALL) || \
    (defined(__CUDA_ARCH_SPECIFIC__) && (__CUDA_ARCH__ == 1030)))
#define EDGE_TC 1
#else
#define EDGE_TC 0
#endif

// ---------------- device scratch (allocation-free) ----------------
__device__ float4 g_accum_f[NN];            // {fx, fy, fz, deg}
__device__ float4 g_accum_msg[NN * 16];     // 64 floats / node

// Pre-swizzled bf16 weight images (exact SMEM layout; linear copy per block)
__device__ uint4 g_W1hi[1536];   // [64 n, 192 k] bf16, SW128 blocked atoms (24576 B)
__device__ uint4 g_W1lo[1536];
__device__ uint4 g_W2hi[512];    // [64, 64]  (8192 B)
__device__ uint4 g_W2lo[512];
__device__ uint4 g_Wc1hi[512];
__device__ uint4 g_Wc1lo[512];

// ---------------- shared helpers ----------------
typedef unsigned long long ull;
__device__ __forceinline__ ull pack2(float v) {
    ull r;
    asm("mov.b64 %0, {%1, %1};" : "=l"(r) : "f"(v));
    return r;
}
__device__ __forceinline__ void unpack2(ull a, float& lo, float& hi) {
    asm("mov.b64 {%0, %1}, %2;" : "=f"(lo), "=f"(hi) : "l"(a));
}
__device__ __forceinline__ void ffma2(ull& acc, ull a, ull b) {
    asm("fma.rn.f32x2 %0, %1, %2, %0;" : "+l"(acc) : "l"(a), "l"(b));
}
__device__ __forceinline__ float silu_f(float x) {
    return __fdividef(x, 1.0f + __expf(-x));
}
__device__ __forceinline__ void red4(float* p, float a, float b, float c, float d) {
    asm volatile("red.global.add.v4.f32 [%0], {%1,%2,%3,%4};"
                 :: "l"(p), "f"(a), "f"(b), "f"(c), "f"(d) : "memory");
}
__device__ __forceinline__ void pf_l1(const void* p) {
    asm volatile("prefetch.global.L1 [%0];" :: "l"(p));
}

// bf16 hi/lo split of a pair (low half of u32 = even-k element 'a')
__device__ __forceinline__ void split2(float a, float b, uint32_t& hi, uint32_t& lo) {
    uint32_t h2;
    asm("cvt.rn.satfinite.bf16x2.f32 %0, %1, %2;" : "=r"(h2) : "f"(b), "f"(a));
    hi = h2;
    float ha = __uint_as_float(h2 << 16);
    float hb = __uint_as_float(h2 & 0xFFFF0000u);
    float la = a - ha, lb = b - hb;
    asm("cvt.rn.satfinite.bf16x2.f32 %0, %1, %2;" : "=r"(lo) : "f"(lb), "f"(la));
}

// swizzled byte offset inside a B weight image [64 rows(n), K cols] blocked-atom SW128
__device__ __forceinline__ uint32_t boff(int n, int k) {
    uint32_t atom = (uint32_t)((k >> 6) * 8 + (n >> 3));
    uint32_t b = atom * 1024u + (uint32_t)(n & 7) * 128u + (uint32_t)(k & 63) * 2u;
    return b ^ ((b >> 3) & 0x70);
}

// ---------------- fp32x2 GEMV helpers (fallback edge + node kernel) ----------------
__device__ __forceinline__ void gemm_row2(ull* a0, ull* a1, const float* wrowhalf,
                                          ull v0, ull v1) {
    const ulonglong2* wr = (const ulonglong2*)wrowhalf;
#pragma unroll
    for (int q = 0; q < 8; q++) {
        ulonglong2 w = wr[q];
        ffma2(a0[2 * q], w.x, v0);
        ffma2(a0[2 * q + 1], w.y, v0);
        ffma2(a1[2 * q], w.x, v1);
        ffma2(a1[2 * q + 1], w.y, v1);
    }
}
__device__ __forceinline__ void gemm4_2(ull* a0, ull* a1, const float* wbase_half,
                                        float4 va, float4 vb) {
    gemm_row2(a0, a1, wbase_half, pack2(va.x), pack2(vb.x));
    gemm_row2(a0, a1, wbase_half + 64, pack2(va.y), pack2(vb.y));
    gemm_row2(a0, a1, wbase_half + 128, pack2(va.z), pack2(vb.z));
    gemm_row2(a0, a1, wbase_half + 192, pack2(va.w), pack2(vb.w));
}
__device__ __forceinline__ void init_bias2(ull* a0, ull* a1, const float* sBhalf) {
    const ulonglong2* bp = (const ulonglong2*)sBhalf;
#pragma unroll
    for (int q = 0; q < 8; q++) {
        ulonglong2 b = bp[q];
        a0[2 * q] = b.x;
        a0[2 * q + 1] = b.y;
        a1[2 * q] = b.x;
        a1[2 * q + 1] = b.y;
    }
}
__device__ __forceinline__ void gemm_row(ull* accp, const float* wrow, ull vv) {
    const ulonglong2* wr = (const ulonglong2*)wrow;
#pragma unroll
    for (int jj = 0; jj < 16; jj++) {
        ulonglong2 w = wr[jj];
        ffma2(accp[2 * jj], w.x, vv);
        ffma2(accp[2 * jj + 1], w.y, vv);
    }
}
__device__ __forceinline__ void gemm4(ull* accp, const float* wbase, float4 sv) {
    gemm_row(accp, wbase, pack2(sv.x));
    gemm_row(accp, wbase + 64, pack2(sv.y));
    gemm_row(accp, wbase + 128, pack2(sv.z));
    gemm_row(accp, wbase + 192, pack2(sv.w));
}
__device__ __forceinline__ void init_bias(ull* accp, const float* sB) {
    const ulonglong2* bp = (const ulonglong2*)sB;
#pragma unroll
    for (int q = 0; q < 16; q++) {
        ulonglong2 b = bp[q];
        accp[2 * q] = b.x;
        accp[2 * q + 1] = b.y;
    }
}

// ---------------- tcgen05 PTX helpers ----------------
__device__ __forceinline__ uint32_t smem_u32(const void* p) {
    uint32_t a;
    asm("{ .reg .u64 t; cvta.to.shared.u64 t, %1; cvt.u32.u64 %0, t; }" : "=r"(a) : "l"(p));
    return a;
}
__device__ __forceinline__ uint32_t elect_one_pred() {
    uint32_t p;
    asm volatile("{\n\t.reg .pred p;\n\telect.sync _|p, 0xFFFFFFFF;\n\tselp.b32 %0, 1, 0, p;\n\t}" : "=r"(p));
    return p;
}

#define TCG_ALLOC(sm, n)  asm volatile("tcgen05.alloc.cta_group::1.sync.aligned.shared::cta.b32 [%0], %1;" :: "r"((uint32_t)(sm)), "r"((uint32_t)(n)) : "memory")
#define TCG_DEALLOC(t, n) asm volatile("tcgen05.dealloc.cta_group::1.sync.aligned.b32 %0, %1;" :: "r"(t), "r"((uint32_t)(n)))
#define TCG_WAIT_ST()     asm volatile("tcgen05.wait::st.sync.aligned;" ::: "memory")
#define TCG_WAIT_LD()     asm volatile("tcgen05.wait::ld.sync.aligned;" ::: "memory")
#define TCG_FENCE_BEFORE() asm volatile("tcgen05.fence::before_thread_sync;" ::: "memory")
#define TCG_FENCE_AFTER()  asm volatile("tcgen05.fence::after_thread_sync;" ::: "memory")
#define TCG_COMMIT(mb)    asm volatile("tcgen05.commit.cta_group::1.mbarrier::arrive::one.shared::cluster.b64 [%0];" :: "r"((uint32_t)(mb)) : "memory")
#define MBAR_INIT(mb, n)  asm volatile("mbarrier.init.shared.b64 [%0], %1;" :: "r"((uint32_t)(mb)), "r"((uint32_t)(n)) : "memory")
#define MBAR_INVAL(mb)    asm volatile("mbarrier.inval.shared.b64 [%0];" :: "r"((uint32_t)(mb)) : "memory")

#define MBAR_WAIT(mb, par) do {                                                      \
    uint32_t _m = (uint32_t)(mb), _p = (uint32_t)(par), _d;                          \
    asm volatile("{\n\t.reg .pred p;\n\t"                                            \
        "mbarrier.try_wait.parity.acquire.cta.shared::cta.b64 p, [%1], %2;\n\t"      \
        "selp.b32 %0, 1, 0, p;\n\t}" : "=r"(_d) : "r"(_m), "r"(_p) : "memory");      \
    if (!_d) {                                                                       \
        asm volatile("{\n\t.reg .pred P1;\n\t"                                       \
            "WL_%=:\n\t"                                                             \
            "mbarrier.try_wait.parity.acquire.cta.shared::cta.b64 P1, [%0], %1, 0x989680;\n\t" \
            "@P1 bra.uni WD_%=;\n\tbra.uni WL_%=;\n\tWD_%=:\n\t}"                    \
            :: "r"(_m), "r"(_p) : "memory");                                         \
    }                                                                                \
} while (0)

#define TCG_ST32(addr, r)                                                            \
    asm volatile("tcgen05.st.sync.aligned.32x32b.x32.b32 [%0], "                     \
        "{%1, %2, %3, %4, %5, %6, %7, %8, %9, %10, %11, %12, %13, %14, %15, %16, "   \
        " %17, %18, %19, %20, %21, %22, %23, %24, %25, %26, %27, %28, %29, %30, %31, %32};" \
        :: "r"(addr),                                                                \
           "r"((r)[0]), "r"((r)[1]), "r"((r)[2]), "r"((r)[3]),                       \
           "r"((r)[4]), "r"((r)[5]), "r"((r)[6]), "r"((r)[7]),                       \
           "r"((r)[8]), "r"((r)[9]), "r"((r)[10]), "r"((r)[11]),                     \
           "r"((r)[12]), "r"((r)[13]), "r"((r)[14]), "r"((r)[15]),                   \
           "r"((r)[16]), "r"((r)[17]), "r"((r)[18]), "r"((r)[19]),                   \
           "r"((r)[20]), "r"((r)[21]), "r"((r)[22]), "r"((r)[23]),                   \
           "r"((r)[24]), "r"((r)[25]), "r"((r)[26]), "r"((r)[27]),                   \
           "r"((r)[28]), "r"((r)[29]), "r"((r)[30]), "r"((r)[31]) : "memory")

#define TCG_ST8(addr, r)                                                             \
    asm volatile("tcgen05.st.sync.aligned.32x32b.x8.b32 [%0], "                      \
        "{%1, %2, %3, %4, %5, %6, %7, %8};"                                          \
        :: "r"(addr),                                                                \
           "r"((r)[0]), "r"((r)[1]), "r"((r)[2]), "r"((r)[3]),                       \
           "r"((r)[4]), "r"((r)[5]), "r"((r)[6]), "r"((r)[7]) : "memory")

#define TCG_ST1(addr, r0)                                                            \
    asm volatile("tcgen05.st.sync.aligned.32x32b.x1.b32 [%0], {%1};"                 \
        :: "r"(addr), "r"(r0) : "memory")

#define TCG_LD32(r, addr)                                                            \
    asm volatile("tcgen05.ld.sync.aligned.32x32b.x32.b32 "                           \
        "{%0, %1, %2, %3, %4, %5, %6, %7, %8, %9, %10, %11, %12, %13, %14, %15, "    \
        " %16, %17, %18, %19, %20, %21, %22, %23, %24, %25, %26, %27, %28, %29, %30, %31}, [%32];" \
        : "=r"((r)[0]), "=r"((r)[1]), "=r"((r)[2]), "=r"((r)[3]),                    \
          "=r"((r)[4]), "=r"((r)[5]), "=r"((r)[6]), "=r"((r)[7]),                    \
          "=r"((r)[8]), "=r"((r)[9]), "=r"((r)[10]), "=r"((r)[11]),                  \
          "=r"((r)[12]), "=r"((r)[13]), "=r"((r)[14]), "=r"((r)[15]),                \
          "=r"((r)[16]), "=r"((r)[17]), "=r"((r)[18]), "=r"((r)[19]),                \
          "=r"((r)[20]), "=r"((r)[21]), "=r"((r)[22]), "=r"((r)[23]),                \
          "=r"((r)[24]), "=r"((r)[25]), "=r"((r)[26]), "=r"((r)[27]),                \
          "=r"((r)[28]), "=r"((r)[29]), "=r"((r)[30]), "=r"((r)[31])                 \
        : "r"(addr))

// idesc kind::f16: F32 dtype, BF16 a/b, N=64 (8<<17), M=128 (8<<24)
#define IDESC_F16 0x8100490u

#if EDGE_TC
__device__ __forceinline__ void mma_f16(uint32_t d, uint32_t a, uint64_t bdesc, bool acc) {
    uint32_t en = acc ? 1u : 0u, z = 0u;
    asm volatile("{\n\t.reg .pred p;\n\tsetp.ne.u32 p, %4, 0;\n\t"
        "tcgen05.mma.cta_group::1.kind::f16 [%0], [%1], %2, %3, {%5, %5, %5, %5}, p;\n\t}"
        :: "r"(d), "r"(a), "l"(bdesc), "r"(IDESC_F16), "r"(en), "r"(z) : "memory");
}
#endif

// SW128 K-major descriptor base (LBO=1, SBO=64, version 1)
static constexpr uint64_t DESC_BASE_SW128 =
    (uint64_t(2) << 61) | (uint64_t(1) << 46) | (uint64_t(64) << 32) | (uint64_t(1) << 16);
__device__ __forceinline__ uint64_t mk_desc(uint32_t addr) {
    return DESC_BASE_SW128 | ((uint64_t)(addr >> 4) & 0x3FFF);
}

// ---------------- zero scratch ----------------
__global__ void zero_kernel() {
    int i = blockIdx.x * blockDim.x + threadIdx.x;
    int stride = gridDim.x * blockDim.x;
    const float4 z = make_float4(0.f, 0.f, 0.f, 0.f);
    for (int k = i; k < NN; k += stride) g_accum_f[k] = z;
    for (int k = i; k < NN * 16; k += stride) g_accum_msg[k] = z;
}

// ---------------- weight prep: transpose + bf16 split + swizzle ----------------
__global__ void prep_kernel(const float* __restrict__ w1e, const float* __restrict__ w2e,
                            const float* __restrict__ wc1) {
    int i = blockIdx.x * blockDim.x + threadIdx.x;
    int stride = gridDim.x * blockDim.x;
    uint8_t* w1h = (uint8_t*)g_W1hi; uint8_t* w1l = (uint8_t*)g_W1lo;
    uint8_t* w2h = (uint8_t*)g_W2hi; uint8_t* w2l = (uint8_t*)g_W2lo;
    uint8_t* wch = (uint8_t*)g_Wc1hi; uint8_t* wcl = (uint8_t*)g_Wc1lo;
    for (int idx = i; idx < 64 * 192; idx += stride) {
        int n = idx / 192, k = idx % 192;
        float f = 0.f;
        if (k <= 143) f = w1e[(1 + k) * 64 + n];
        else if (k == 144) f = w1e[n];
        __nv_bfloat16 h = __float2bfloat16(f);
        float lo = f - __bfloat162float(h);
        uint32_t o = boff(n, k);
        *(__nv_bfloat16*)(w1h + o) = h;
        *(__nv_bfloat16*)(w1l + o) = __float2bfloat16(lo);
    }
    for (int idx = i; idx < 64 * 64; idx += stride) {
        int n = idx / 64, k = idx % 64;
        uint32_t o = boff(n, k);
        float f = w2e[k * 64 + n];
        __nv_bfloat16 h = __float2bfloat16(f);
        *(__nv_bfloat16*)(w2h + o) = h;
        *(__nv_bfloat16*)(w2l + o) = __float2bfloat16(f - __bfloat162float(h));
        float g = wc1[k * 64 + n];
        __nv_bfloat16 hg = __float2bfloat16(g);
        *(__nv_bfloat16*)(wch + o) = hg;
        *(__nv_bfloat16*)(wcl + o) = __float2bfloat16(g - __bfloat162float(hg));
    }
}

// ---------------- edge kernel: PERSISTENT tcgen05 or fp32x2 fallback ----------------
// TMEM (256 cols): A1 hi 0..95 | A1 lo 96..191 | D region 192..255 (D1, D2, D3 in turn)
// A2 reuses 0..63 (hi 0..31, lo 32..63); A3 reuses 128..191 (hi 128..159, lo 160..191).
// Cols 64..72 = chunk2 (ef+sq); 73..95 stay ZERO forever (one-time init, never clobbered
// since D2 lives in the 192..255 D region).
#define SO_TMEM 0
#define SO_MBAR 8
#define SO_B1   16
#define SO_B2   272
#define SO_BC1  528
#define SO_WC2  784
#define SO_W1HI 4096
#define SO_W1LO 28672
#define SO_W2HI 53248
#define SO_W2LO 61440
#define SO_WC1HI 69632
#define SO_WC1LO 77824
#define EDGE_SMEM_BYTES ((9280 + 4096 + 4096 + 4 * 64 + 64 * 128) * 4)   // 103680 >= 86016

__global__ __launch_bounds__(128, 2) void edge_kernel(
    const float* __restrict__ x, const float* __restrict__ h,
    const float* __restrict__ edge_fea,
    const float* __restrict__ w1e, const float* __restrict__ b1e,
    const float* __restrict__ w2e, const float* __restrict__ b2e,
    const float* __restrict__ wc1, const float* __restrict__ bc1,
    const float* __restrict__ wc2, const float* __restrict__ bc2,
    const int* __restrict__ row, const int* __restrict__ col) {
#if EDGE_TC
    // ================= persistent tcgen05 path =================
    extern __shared__ uint8_t sm[];
    const uint32_t smb = smem_u32(sm);
    const int tid = threadIdx.x;
    const int wid = tid >> 5;
    const uint32_t woff = (uint32_t)wid << 21;

    // one-time staging
    {
        uint4* d;
        d = (uint4*)(sm + SO_W1HI);
        for (int i = tid; i < 1536; i += 128) d[i] = g_W1hi[i];
        d = (uint4*)(sm + SO_W1LO);
        for (int i = tid; i < 1536; i += 128) d[i] = g_W1lo[i];
        d = (uint4*)(sm + SO_W2HI);
        for (int i = tid; i < 512; i += 128) d[i] = g_W2hi[i];
        d = (uint4*)(sm + SO_W2LO);
        for (int i = tid; i < 512; i += 128) d[i] = g_W2lo[i];
        d = (uint4*)(sm + SO_WC1HI);
        for (int i = tid; i < 512; i += 128) d[i] = g_Wc1hi[i];
        d = (uint4*)(sm + SO_WC1LO);
        for (int i = tid; i < 512; i += 128) d[i] = g_Wc1lo[i];
    }
    float* sB1 = (float*)(sm + SO_B1);
    float* sB2 = (float*)(sm + SO_B2);
    float* sBc1 = (float*)(sm + SO_BC1);
    float* sWc2 = (float*)(sm + SO_WC2);
    if (tid < 64) {
        sB1[tid] = b1e[tid];
        sB2[tid] = b2e[tid];
        sBc1[tid] = bc1[tid];
        sWc2[tid] = wc2[tid];
    }
    if (wid == 0) TCG_ALLOC(smb + SO_TMEM, 256);
    if (tid == 0) MBAR_INIT(smb + SO_MBAR, 1);
    __syncthreads();
    uint32_t tb;
    asm volatile("ld.shared.b32 %0, [%1];" : "=r"(tb) : "r"(smb + SO_TMEM));

    const uint64_t dW1h = mk_desc(smb + SO_W1HI);
    const uint64_t dW1l = mk_desc(smb + SO_W1LO);
    const uint64_t dW2h = mk_desc(smb + SO_W2HI);
    const uint64_t dW2l = mk_desc(smb + SO_W2LO);
    const uint64_t dWch = mk_desc(smb + SO_WC1HI);
    const uint64_t dWcl = mk_desc(smb + SO_WC1LO);
    const float bc2v = __ldg(bc2);

    // one-time zero of chunk-2 tail columns (cols 64..95 hi, 160..191 lo).
    // Cols 73..95 are never written again (D2 lives at 192..255), so they stay
    // exactly zero; cols 169..191 are refreshed by A3 each tile (finite bf16).
    {
        uint32_t z[32];
#pragma unroll
        for (int q = 0; q < 32; q++) z[q] = 0u;
        TCG_ST32(tb + 64 + woff, z);
        TCG_ST32(tb + 160 + woff, z);
        TCG_WAIT_ST();
    }

    uint32_t wp = 0;   // running mbarrier wait counter (parity = wp & 1)

    // ---- prologue prefetch for the first tile ----
    int t = blockIdx.x;
    int r, c;
    float rx, ry, rz, sq;
    float4 ef0, ef1, ef2, ef3;
    {
        const int e = t * 128 + tid;
        r = row[e];
        c = col[e];
        rx = x[3 * r] - x[3 * c];
        ry = x[3 * r + 1] - x[3 * c + 1];
        rz = x[3 * r + 2] - x[3 * c + 2];
        sq = rx * rx + ry * ry + rz * rz;
        const float4* ef = (const float4*)(edge_fea + (size_t)e * 16);
        ef0 = __ldg(ef);
        ef1 = __ldg(ef + 1);
        ef2 = __ldg(ef + 2);
        ef3 = __ldg(ef + 3);
        pf_l1(h + (size_t)r * HD);
        pf_l1(h + (size_t)r * HD + 32);
        pf_l1(h + (size_t)c * HD);
        pf_l1(h + (size_t)c * HD + 32);
    }

    for (; t < NB; t += EDGE_GRID) {
        // ---- A1 build (TMEM cols 0..191) ----
        {
            uint32_t ahi[32], alo[32];
            const float4* hr = (const float4*)(h + (size_t)r * HD);
#pragma unroll
            for (int q = 0; q < 16; q++) {
                float4 v = __ldg(hr + q);
                split2(v.x, v.y, ahi[2 * q], alo[2 * q]);
                split2(v.z, v.w, ahi[2 * q + 1], alo[2 * q + 1]);
            }
            TCG_ST32(tb + 0 + woff, ahi);
            TCG_ST32(tb + 96 + woff, alo);
            const float4* hc = (const float4*)(h + (size_t)c * HD);
#pragma unroll
            for (int q = 0; q < 16; q++) {
                float4 v = __ldg(hc + q);
                split2(v.x, v.y, ahi[2 * q], alo[2 * q]);
                split2(v.z, v.w, ahi[2 * q + 1], alo[2 * q + 1]);
            }
            TCG_ST32(tb + 32 + woff, ahi);
            TCG_ST32(tb + 96 + 32 + woff, alo);
            // chunk2: ef (8 cols) + sq (1 col); tail cols stay zero / finite-x-zero-weight
            split2(ef0.x, ef0.y, ahi[0], alo[0]);
            split2(ef0.z, ef0.w, ahi[1], alo[1]);
            split2(ef1.x, ef1.y, ahi[2], alo[2]);
            split2(ef1.z, ef1.w, ahi[3], alo[3]);
            split2(ef2.x, ef2.y, ahi[4], alo[4]);
            split2(ef2.z, ef2.w, ahi[5], alo[5]);
            split2(ef3.x, ef3.y, ahi[6], alo[6]);
            split2(ef3.z, ef3.w, ahi[7], alo[7]);
            split2(sq, 0.f, ahi[8], alo[8]);
            TCG_ST8(tb + 64 + woff, ahi);
            TCG_ST1(tb + 72 + woff, ahi[8]);
            TCG_ST8(tb + 160 + woff, alo);
            TCG_ST1(tb + 168 + woff, alo[8]);
            TCG_WAIT_ST();
        }
        TCG_FENCE_BEFORE();
        __syncthreads();

        // ---- GEMM1: D1(192) = A1 @ W1^T, K=192, 3 bf16 splits ----
        if (wid == 0) {
            TCG_FENCE_AFTER();
            if (elect_one_pred()) {
#pragma unroll
                for (int k = 0; k < 12; k++)
                    mma_f16(tb + 192, tb + 8 * k, dW1h + (uint64_t)((k >> 2) * 512 + (k & 3) * 2), k > 0);
#pragma unroll
                for (int k = 0; k < 12; k++)
                    mma_f16(tb + 192, tb + 8 * k, dW1l + (uint64_t)((k >> 2) * 512 + (k & 3) * 2), true);
#pragma unroll
                for (int k = 0; k < 12; k++)
                    mma_f16(tb + 192, tb + 96 + 8 * k, dW1h + (uint64_t)((k >> 2) * 512 + (k & 3) * 2), true);
                TCG_COMMIT(smb + SO_MBAR);
            }
        }

        // ---- prefetch next tile during the MMA1 wait ----
        int rn, cn;
        float rxn, ryn, rzn, sqn;
        float4 en0, en1, en2, en3;
        {
            const int tn = t + EDGE_GRID;
            const int ts = (tn < NB) ? tn : t;   // safe addr; values unused past loop end
            const int e2 = ts * 128 + tid;
            rn = row[e2];
            cn = col[e2];
            rxn = x[3 * rn] - x[3 * cn];
            ryn = x[3 * rn + 1] - x[3 * cn + 1];
            rzn = x[3 * rn + 2] - x[3 * cn + 2];
            sqn = rxn * rxn + ryn * ryn + rzn * rzn;
            const float4* ef = (const float4*)(edge_fea + (size_t)e2 * 16);
            en0 = __ldg(ef);
            en1 = __ldg(ef + 1);
            en2 = __ldg(ef + 2);
            en3 = __ldg(ef + 3);
            pf_l1(h + (size_t)rn * HD);
            pf_l1(h + (size_t)rn * HD + 32);
            pf_l1(h + (size_t)cn * HD);
            pf_l1(h + (size_t)cn * HD + 32);
        }

        MBAR_WAIT(smb + SO_MBAR, wp & 1);
        wp++;
        TCG_FENCE_AFTER();

        // ---- epilogue 1: t1 = silu(D1 + b1); A2 = split(t1) -> cols 0..63 ----
        {
            uint32_t d0[32], d1[32];
            TCG_LD32(d0, tb + 192);
            TCG_LD32(d1, tb + 224);
            TCG_WAIT_LD();
            float tt[64];
#pragma unroll
            for (int n = 0; n < 32; n++) tt[n] = silu_f(__uint_as_float(d0[n]) + sB1[n]);
#pragma unroll
            for (int n = 0; n < 32; n++) tt[32 + n] = silu_f(__uint_as_float(d1[n]) + sB1[32 + n]);
            uint32_t ahi[32], alo[32];
#pragma unroll
            for (int q = 0; q < 32; q++) split2(tt[2 * q], tt[2 * q + 1], ahi[q], alo[q]);
            TCG_ST32(tb + 0 + woff, ahi);
            TCG_ST32(tb + 32 + woff, alo);
            TCG_WAIT_ST();
        }
        TCG_FENCE_BEFORE();
        __syncthreads();

        // ---- GEMM2: D2(192) = A2 @ W2^T, K=64 (reuses the 192..255 D region;
        //      epilogue-1's LDTMs of D1 drained before the barrier above) ----
        if (wid == 0) {
            TCG_FENCE_AFTER();
            if (elect_one_pred()) {
#pragma unroll
                for (int k = 0; k < 4; k++) mma_f16(tb + 192, tb + 8 * k, dW2h + 2 * k, k > 0);
#pragma unroll
                for (int k = 0; k < 4; k++) mma_f16(tb + 192, tb + 8 * k, dW2l + 2 * k, true);
#pragma unroll
                for (int k = 0; k < 4; k++) mma_f16(tb + 192, tb + 32 + 8 * k, dW2h + 2 * k, true);
                TCG_COMMIT(smb + SO_MBAR);
            }
        }
        MBAR_WAIT(smb + SO_MBAR, wp & 1);
        wp++;
        TCG_FENCE_AFTER();

        // ---- epilogue 2: msg = silu(D2 + b2); A3 = split(msg) -> cols 128..191 ----
        float tt[64];
        {
            uint32_t d0[32], d1[32];
            TCG_LD32(d0, tb + 192);
            TCG_LD32(d1, tb + 224);
            TCG_WAIT_LD();
#pragma unroll
            for (int n = 0; n < 32; n++) tt[n] = silu_f(__uint_as_float(d0[n]) + sB2[n]);
#pragma unroll
            for (int n = 0; n < 32; n++) tt[32 + n] = silu_f(__uint_as_float(d1[n]) + sB2[32 + n]);
            uint32_t ahi[32], alo[32];
#pragma unroll
            for (int q = 0; q < 32; q++) split2(tt[2 * q], tt[2 * q + 1], ahi[q], alo[q]);
            TCG_ST32(tb + 128 + woff, ahi);
            TCG_ST32(tb + 160 + woff, alo);
            TCG_WAIT_ST();
        }
        TCG_FENCE_BEFORE();
        __syncthreads();

        // ---- GEMM3: D3(192) = A3 @ Wc1^T, K=64 ----
        if (wid == 0) {
            TCG_FENCE_AFTER();
            if (elect_one_pred()) {
#pragma unroll
                for (int k = 0; k < 4; k++) mma_f16(tb + 192, tb + 128 + 8 * k, dWch + 2 * k, k > 0);
#pragma unroll
                for (int k = 0; k < 4; k++) mma_f16(tb + 192, tb + 128 + 8 * k, dWcl + 2 * k, true);
#pragma unroll
                for (int k = 0; k < 4; k++) mma_f16(tb + 192, tb + 160 + 8 * k, dWch + 2 * k, true);
                TCG_COMMIT(smb + SO_MBAR);
            }
        }

        // ---- msg atomics in the MMA3 shadow ----
        {
            float* msgp = (float*)g_accum_msg + (size_t)r * HD;
#pragma unroll
            for (int q = 0; q < 16; q++)
                red4(msgp + 4 * q, tt[4 * q], tt[4 * q + 1], tt[4 * q + 2], tt[4 * q + 3]);
        }

        MBAR_WAIT(smb + SO_MBAR, wp & 1);
        wp++;
        TCG_FENCE_AFTER();

        // ---- epilogue 3: csum = silu(D3 + bc1) . wc2 + bc2 ; force atomic ----
        {
            uint32_t d0[32], d1[32];
            TCG_LD32(d0, tb + 192);
            TCG_LD32(d1, tb + 224);
            TCG_WAIT_LD();
            float csum = bc2v;
#pragma unroll
            for (int n = 0; n < 32; n++) csum += silu_f(__uint_as_float(d0[n]) + sBc1[n]) * sWc2[n];
#pragma unroll
            for (int n = 0; n < 32; n++)
                csum += silu_f(__uint_as_float(d1[n]) + sBc1[32 + n]) * sWc2[32 + n];
            red4((float*)g_accum_f + (size_t)4 * r, rx * csum, ry * csum, rz * csum, 1.0f);
        }

        // rotate prefetched tile -> current (no loop-end sync needed: next A-build
        // cols 0..191 are disjoint from the D region 192..255, GEMM3 completed
        // before epilogue 3, and the pre-MMA1 barrier orders all warps' LDTMs)
        r = rn; c = cn;
        rx = rxn; ry = ryn; rz = rzn; sq = sqn;
        ef0 = en0; ef1 = en1; ef2 = en2; ef3 = en3;
    }

    __syncthreads();
    if (tid == 0) MBAR_INVAL(smb + SO_MBAR);
    __syncthreads();
    if (wid == 0) TCG_DEALLOC(tb, 256);

#else
    // ================= persistent fp32x2 fallback =================
    extern __shared__ uint8_t sm8[];
    float* smf = (float*)sm8;
    float* sW1 = smf;                  // [145][64]
    float* sW2 = smf + 9280;           // [64][64]
    float* sWc1 = smf + 13376;         // [64][64]
    float* sWc2 = smf + 17472;         // 64
    float* sB1 = smf + 17536;
    float* sB2 = smf + 17600;
    float* sBc1 = smf + 17664;
    float* tbuf = smf + 17728;         // [64][128]

    int tid = threadIdx.x;
    for (int i = tid; i < 9280; i += 128) sW1[i] = w1e[i];
    for (int i = tid; i < 4096; i += 128) sW2[i] = w2e[i];
    for (int i = tid; i < 4096; i += 128) sWc1[i] = wc1[i];
    if (tid < 64) {
        sWc2[tid] = wc2[tid];
        sB1[tid] = b1e[tid];
        sB2[tid] = b2e[tid];
        sBc1[tid] = bc1[tid];
    }
    __syncthreads();

    const int half = tid >> 6;
    const int j = tid & 63;
    const int hoff = half * 32;
    const float bc2v = __ldg(bc2);

    for (int t = blockIdx.x; t < NB; t += EDGE_GRID) {
        __syncthreads();
        const int e0 = t * 128 + 2 * j;

        int2 rr = *(const int2*)(row + e0);
        int2 cc = *(const int2*)(col + e0);
        const int r0 = rr.x, r1 = rr.y;
        const int c0 = cc.x, c1 = cc.y;

        float rx0 = x[3 * r0] - x[3 * c0];
        float ry0 = x[3 * r0 + 1] - x[3 * c0 + 1];
        float rz0 = x[3 * r0 + 2] - x[3 * c0 + 2];
        float rx1 = x[3 * r1] - x[3 * c1];
        float ry1 = x[3 * r1 + 1] - x[3 * c1 + 1];
        float rz1 = x[3 * r1 + 2] - x[3 * c1 + 2];
        float sq0 = rx0 * rx0 + ry0 * ry0 + rz0 * rz0;
        float sq1 = rx1 * rx1 + ry1 * ry1 + rz1 * rz1;

        ull acc0[16], acc1[16];

        const float* W1 = sW1 + hoff;
        init_bias2(acc0, acc1, sB1 + hoff);
        gemm_row2(acc0, acc1, W1, pack2(sq0), pack2(sq1));
        {
            const float4* hr0 = (const float4*)(h + (size_t)r0 * HD);
            const float4* hr1 = (const float4*)(h + (size_t)r1 * HD);
#pragma unroll 2
            for (int k = 0; k < 16; k++)
                gemm4_2(acc0, acc1, W1 + (1 + 4 * k) * 64, __ldg(hr0 + k), __ldg(hr1 + k));
            const float4* hc0 = (const float4*)(h + (size_t)c0 * HD);
            const float4* hc1 = (const float4*)(h + (size_t)c1 * HD);
#pragma unroll 2
            for (int k = 0; k < 16; k++)
                gemm4_2(acc0, acc1, W1 + (65 + 4 * k) * 64, __ldg(hc0 + k), __ldg(hc1 + k));
            const float4* ef0p = (const float4*)(edge_fea + (size_t)e0 * 16);
            const float4* ef1p = (const float4*)(edge_fea + (size_t)(e0 + 1) * 16);
#pragma unroll 2
            for (int k = 0; k < 4; k++)
                gemm4_2(acc0, acc1, W1 + (129 + 4 * k) * 64, __ldg(ef0p + k), __ldg(ef1p + k));
        }
#pragma unroll
        for (int q = 0; q < 16; q++) {
            float a, b, c, d;
            unpack2(acc0[q], a, b);
            unpack2(acc1[q], c, d);
            int f = hoff + 2 * q;
            *(float2*)&tbuf[f * 128 + 2 * j] = make_float2(silu_f(a), silu_f(c));
            *(float2*)&tbuf[(f + 1) * 128 + 2 * j] = make_float2(silu_f(b), silu_f(d));
        }
        __syncthreads();

        init_bias2(acc0, acc1, sB2 + hoff);
#pragma unroll 2
        for (int i = 0; i < 64; i++) {
            float2 tv = *(const float2*)&tbuf[i * 128 + 2 * j];
            gemm_row2(acc0, acc1, sW2 + i * 64 + hoff, pack2(tv.x), pack2(tv.y));
        }
        __syncthreads();

        {
            float* msgp0 = (float*)g_accum_msg + (size_t)r0 * HD + hoff;
            float* msgp1 = (float*)g_accum_msg + (size_t)r1 * HD + hoff;
#pragma unroll
            for (int q = 0; q < 8; q++) {
                float a0v, a1v, a2v, a3v, b0v, b1v, b2v, b3v;
                unpack2(acc0[2 * q], a0v, a1v);
                unpack2(acc0[2 * q + 1], a2v, a3v);
                unpack2(acc1[2 * q], b0v, b1v);
                unpack2(acc1[2 * q + 1], b2v, b3v);
                a0v = silu_f(a0v); a1v = silu_f(a1v); a2v = silu_f(a2v); a3v = silu_f(a3v);
                b0v = silu_f(b0v); b1v = silu_f(b1v); b2v = silu_f(b2v); b3v = silu_f(b3v);
                int f = hoff + 4 * q;
                *(float2*)&tbuf[f * 128 + 2 * j] = make_float2(a0v, b0v);
                *(float2*)&tbuf[(f + 1) * 128 + 2 * j] = make_float2(a1v, b1v);
                *(float2*)&tbuf[(f + 2) * 128 + 2 * j] = make_float2(a2v, b2v);
                *(float2*)&tbuf[(f + 3) * 128 + 2 * j] = make_float2(a3v, b3v);
                red4(msgp0 + 4 * q, a0v, a1v, a2v, a3v);
                red4(msgp1 + 4 * q, b0v, b1v, b2v, b3v);
            }
        }
        __syncthreads();

        init_bias2(acc0, acc1, sBc1 + hoff);
#pragma unroll 2
        for (int i = 0; i < 64; i++) {
            float2 tv = *(const float2*)&tbuf[i * 128 + 2 * j];
            gemm_row2(acc0, acc1, sWc1 + i * 64 + hoff, pack2(tv.x), pack2(tv.y));
        }

        float p0 = 0.f, p1 = 0.f;
#pragma unroll
        for (int q = 0; q < 16; q++) {
            float a, b, c, d;
            unpack2(acc0[q], a, b);
            unpack2(acc1[q], c, d);
            float w0 = sWc2[hoff + 2 * q], w1v = sWc2[hoff + 2 * q + 1];
            p0 += silu_f(a) * w0 + silu_f(b) * w1v;
            p1 += silu_f(c) * w0 + silu_f(d) * w1v;
        }
        __syncthreads();
        tbuf[(2 * j) * 2 + half] = p0;
        tbuf[(2 * j + 1) * 2 + half] = p1;
        __syncthreads();

        int m = 2 * j + half;
        float csum = tbuf[m * 2] + tbuf[m * 2 + 1] + bc2v;
        float rxm = half ? rx1 : rx0;
        float rym = half ? ry1 : ry0;
        float rzm = half ? rz1 : rz0;
        int rm = half ? r1 : r0;
        red4((float*)g_accum_f + (size_t)4 * rm, rxm * csum, rym * csum, rzm * csum, 1.0f);
    }
#endif
}

// ---------------- node kernel (fp32x2, unchanged) ----------------
#define NODE_SMEM_FLOATS (8192 + 4096 + 64 + 64 + 64 * 128)
#define NODE_SMEM_BYTES (NODE_SMEM_FLOATS * 4)

__global__ __launch_bounds__(128, 2) void node_kernel(
    const float* __restrict__ x, const float* __restrict__ h,
    const float* __restrict__ wn1, const float* __restrict__ bn1,
    const float* __restrict__ wn2, const float* __restrict__ bn2,
    float* __restrict__ out) {
    extern __shared__ float smf[];
    float* sWn1 = smf;
    float* sWn2 = smf + 8192;
    float* sBn1 = smf + 12288;
    float* sBn2 = smf + 12352;
    float* tbuf = smf + 12416;

    int tid = threadIdx.x;
    for (int i = tid; i < 8192; i += 128) sWn1[i] = wn1[i];
    for (int i = tid; i < 4096; i += 128) sWn2[i] = wn2[i];
    if (tid < 64) {
        sBn1[tid] = bn1[tid];
        sBn2[tid] = bn2[tid];
    }
    __syncthreads();

    int v = blockIdx.x * 128 + tid;
    if (v >= NN) return;

    ull accp[32];
    init_bias(accp, sBn1);
    const float4* hv = (const float4*)(h + (size_t)v * HD);
#pragma unroll 2
    for (int k = 0; k < 16; k++) gemm4(accp, sWn1 + (4 * k) * 64, __ldg(hv + k));
    const float4* mv = (const float4*)((const float*)g_accum_msg + (size_t)v * HD);
#pragma unroll 2
    for (int k = 0; k < 16; k++) gemm4(accp, sWn1 + (64 + 4 * k) * 64, __ldg(mv + k));

#pragma unroll
    for (int p = 0; p < 32; p++) {
        float lo, hi;
        unpack2(accp[p], lo, hi);
        tbuf[(2 * p) * 128 + tid] = silu_f(lo);
        tbuf[(2 * p + 1) * 128 + tid] = silu_f(hi);
    }

    init_bias(accp, sBn2);
#pragma unroll 2
    for (int i = 0; i < 64; i++) gemm_row(accp, sWn2 + i * 64, pack2(tbuf[i * 128 + tid]));

    float* out_h = out + (size_t)NN * 3;
#pragma unroll
    for (int p = 0; p < 16; p++) {
        float a0, a1, a2, a3;
        unpack2(accp[2 * p], a0, a1);
        unpack2(accp[2 * p + 1], a2, a3);
        *(float4*)(out_h + (size_t)v * HD + 4 * p) = make_float4(a0, a1, a2, a3);
    }

    float4 af = g_accum_f[v];
    float deg = fmaxf(af.w, 1.0f);
    float fx = fminf(fmaxf(af.x / deg, -100.f), 100.f);
    float fy = fminf(fmaxf(af.y / deg, -100.f), 100.f);
    float fz = fminf(fmaxf(af.z / deg, -100.f), 100.f);
    out[3 * v + 0] = x[3 * v + 0] + fx;
    out[3 * v + 1] = x[3 * v + 1] + fy;
    out[3 * v + 2] = x[3 * v + 2] + fz;
}

// ---------------- launch ----------------
extern "C" void kernel_launch(void* const* d_in, const int* in_sizes, int n_in,
                              void* d_out, int out_size) {
    const float* x = (const float*)d_in[0];
    const float* h = (const float*)d_in[1];
    const float* edge_fea = (const float*)d_in[2];
    const float* w1e = (const float*)d_in[3];
    const float* b1e = (const float*)d_in[4];
    const float* w2e = (const float*)d_in[5];
    const float* b2e = (const float*)d_in[6];
    const float* wc1 = (const float*)d_in[7];
    const float* bc1 = (const float*)d_in[8];
    const float* wc2 = (const float*)d_in[9];
    const float* bc2 = (const float*)d_in[10];
    const float* wn1 = (const float*)d_in[11];
    const float* bn1 = (const float*)d_in[12];
    const float* wn2 = (const float*)d_in[13];
    const float* bn2 = (const float*)d_in[14];
    const int* row = (const int*)d_in[15];
    const int* col = (const int*)d_in[16];
    float* out = (float*)d_out;

    cudaFuncSetAttribute(edge_kernel, cudaFuncAttributeMaxDynamicSharedMemorySize,
                         EDGE_SMEM_BYTES);
    cudaFuncSetAttribute(node_kernel, cudaFuncAttributeMaxDynamicSharedMemorySize,
                         NODE_SMEM_BYTES);

    zero_kernel<<<512, 256>>>();
    prep_kernel<<<64, 256>>>(w1e, w2e, wc1);
    edge_kernel<<<EDGE_GRID, 128, EDGE_SMEM_BYTES>>>(x, h, edge_fea, w1e, b1e, w2e, b2e,
                                                     wc1, bc1, wc2, bc2, row, col);
    node_kernel<<<(NN + 127) / 128, 128, NODE_SMEM_BYTES>>>(x, h, wn1, bn1, wn2, bn2, out);
}